// round 1
// baseline (speedup 1.0000x reference)
#include <cuda_runtime.h>
#include <math.h>

#define HTOT 87296
#define NANCH 261888
#define PRE_NMS_N 6000
#define POST_NMS_N 300
#define NEGV -1000000000.0f
#define TIE_CAP 16384

// ---------------- device scratch (static globals: allocation-free) ----------------
static __device__ __align__(16) float g_h[(size_t)256 * HTOT];      // relu(conv3x3) activations [oc][pix]
static __device__ float4 g_boxes[NANCH];
static __device__ float  g_scores[NANCH];
static __device__ float4 g_tb[PRE_NMS_N];
static __device__ float  g_ts[PRE_NMS_N];
static __device__ int    g_ti[PRE_NMS_N];
static __device__ unsigned int g_hist[256];
static __device__ unsigned int g_prefix, g_above, g_remain;
static __device__ int g_ctr, g_tiectr;
static __device__ int g_ties[TIE_CAP];

// ---------------- conv3x3 + relu ----------------
// Block: 256 threads computes 64 output channels x 256 pixels (TH rows x W cols).
// Thread: 4 oc x 16 pixels (4 groups of 4 consecutive) = 64 fp32 accumulators.
template<int W>
__global__ __launch_bounds__(256, 2) void conv3x3_relu(
    const float* __restrict__ x, const float* __restrict__ w,
    const float* __restrict__ bias, int lvl_off)
{
    constexpr int H = W;
    constexpr int TH = 256 / W;
    constexpr int XP = W + 2;
    constexpr int XROWS = TH + 2;
    __shared__ float Xs[4][XROWS][XP];
    __shared__ __align__(16) float Ws[4][9][64];

    const int t   = threadIdx.x;
    const int r0  = blockIdx.x * TH;
    const int ocb = blockIdx.y * 64;
    const int tp  = t & 15;
    const int to  = t >> 4;

    int pr[4], pc[4];
#pragma unroll
    for (int g = 0; g < 4; g++) {
        int p = tp * 4 + g * 64;
        pr[g] = p / W;
        pc[g] = p % W;
    }

    float acc[4][4][4];
#pragma unroll
    for (int g = 0; g < 4; g++)
#pragma unroll
        for (int j = 0; j < 4; j++)
#pragma unroll
            for (int o = 0; o < 4; o++) acc[g][j][o] = 0.f;

    const int wo  = t >> 2;   // 0..63
    const int wic = t & 3;    // 0..3

    for (int ic0 = 0; ic0 < 256; ic0 += 4) {
        __syncthreads();
        // load input tile (+halo, zero padded)
        for (int i = t; i < 4 * XROWS * XP; i += 256) {
            int icc = i / (XROWS * XP);
            int rem = i - icc * (XROWS * XP);
            int ry  = rem / XP;
            int rx  = rem - ry * XP;
            int gy  = r0 + ry - 1;
            int gx  = rx - 1;
            float v = 0.f;
            if (gy >= 0 && gy < H && gx >= 0 && gx < W)
                v = x[(size_t)(ic0 + icc) * (H * W) + gy * W + gx];
            Xs[icc][ry][rx] = v;
        }
        // load weights: Ws[icc][tap][oc]
        {
            const float* wp = w + (size_t)(ocb + wo) * 2304 + (ic0 + wic) * 9;
#pragma unroll
            for (int tap = 0; tap < 9; tap++) Ws[wic][tap][wo] = wp[tap];
        }
        __syncthreads();

#pragma unroll
        for (int icc = 0; icc < 4; icc++) {
#pragma unroll
            for (int ky = 0; ky < 3; ky++) {
                float xr[4][6];
#pragma unroll
                for (int g = 0; g < 4; g++)
#pragma unroll
                    for (int k = 0; k < 6; k++)
                        xr[g][k] = Xs[icc][pr[g] + ky][pc[g] + k];
#pragma unroll
                for (int kx = 0; kx < 3; kx++) {
                    float4 wv = *(const float4*)&Ws[icc][ky * 3 + kx][to * 4];
                    float wa[4] = {wv.x, wv.y, wv.z, wv.w};
#pragma unroll
                    for (int g = 0; g < 4; g++)
#pragma unroll
                        for (int j = 0; j < 4; j++) {
                            float xv = xr[g][j + kx];
#pragma unroll
                            for (int o = 0; o < 4; o++)
                                acc[g][j][o] = fmaf(xv, wa[o], acc[g][j][o]);
                        }
                }
            }
        }
    }

    // epilogue: bias + relu, vectorized store
#pragma unroll
    for (int o = 0; o < 4; o++) {
        int oc = ocb + to * 4 + o;
        float bv = bias[oc];
        float* hp = g_h + (size_t)oc * HTOT + lvl_off;
#pragma unroll
        for (int g = 0; g < 4; g++) {
            float4 v;
            v.x = fmaxf(acc[g][0][o] + bv, 0.f);
            v.y = fmaxf(acc[g][1][o] + bv, 0.f);
            v.z = fmaxf(acc[g][2][o] + bv, 0.f);
            v.w = fmaxf(acc[g][3][o] + bv, 0.f);
            *(float4*)(hp + (r0 + pr[g]) * W + pc[g]) = v;
        }
    }
}

// ---------------- heads: 1x1 convs + softmax + anchor decode + min-size filter --------
__global__ __launch_bounds__(128) void heads_decode(
    const float* __restrict__ lw, const float* __restrict__ lb,
    const float* __restrict__ sw, const float* __restrict__ sb)
{
    __shared__ float WL[12][256];
    __shared__ float WS[6][256];
    __shared__ float BL[12], BS[6];
    const int t = threadIdx.x;
    for (int i = t; i < 12 * 256; i += 128) WL[i >> 8][i & 255] = lw[i];
    for (int i = t; i < 6 * 256; i += 128)  WS[i >> 8][i & 255] = sw[i];
    if (t < 12) BL[t] = lb[t];
    if (t < 6)  BS[t] = sb[t];
    __syncthreads();

    const int pix = blockIdx.x * 128 + t;   // 0..87295 (grid exact)
    int lvl;
    if (pix < 65536) lvl = 0;
    else if (pix < 81920) lvl = 1;
    else if (pix < 86016) lvl = 2;
    else if (pix < 87040) lvl = 3;
    else lvl = 4;
    const int offs[5] = {0, 65536, 81920, 86016, 87040};
    const int lp   = pix - offs[lvl];
    const int lw2  = 8 - lvl;             // log2(W)
    const int row  = lp >> lw2;
    const int col  = lp & ((1 << lw2) - 1);
    const int strd = 4 << lvl;

    float acc[18];
#pragma unroll
    for (int j = 0; j < 12; j++) acc[j] = BL[j];
#pragma unroll
    for (int j = 0; j < 6; j++)  acc[12 + j] = BS[j];

    const float* hp = g_h + pix;
#pragma unroll 4
    for (int ic = 0; ic < 256; ic++) {
        float v = hp[(size_t)ic * HTOT];
#pragma unroll
        for (int j = 0; j < 12; j++) acc[j] = fmaf(WL[j][ic], v, acc[j]);
#pragma unroll
        for (int j = 0; j < 6; j++)  acc[12 + j] = fmaf(WS[j][ic], v, acc[12 + j]);
    }

    const float y  = (float)(row * strd);
    const float xx = (float)(col * strd);
    const float sr[3] = {0.70710678118654752f, 1.0f, 1.41421356237309505f};
#pragma unroll
    for (int a = 0; a < 3; a++) {
        float hs = (float)(strd * 8) * sr[a];
        float ws = (float)(strd * 8) * sr[2 - a];
        // anchor exactly as reference (separate rounds, no fma contraction)
        float a0 = __fadd_rn(y,  -0.5f * hs);
        float a1 = __fadd_rn(xx, -0.5f * ws);
        float a2 = __fadd_rn(y,   0.5f * hs);
        float a3 = __fadd_rn(xx,  0.5f * ws);
        float ah = __fadd_rn(a2, -a0);
        float aw = __fadd_rn(a3, -a1);
        float acy = __fadd_rn(a0, __fmul_rn(0.5f, ah));
        float acx = __fadd_rn(a1, __fmul_rn(0.5f, aw));
        float dy = acc[a * 4 + 0], dx = acc[a * 4 + 1];
        float dh = acc[a * 4 + 2], dw = acc[a * 4 + 3];
        float cy = __fadd_rn(__fmul_rn(dy, ah), acy);
        float cx = __fadd_rn(__fmul_rn(dx, aw), acx);
        float bh = __fmul_rn(expf(dh), ah);
        float bw = __fmul_rn(expf(dw), aw);
        float b0 = fminf(fmaxf(__fadd_rn(cy, -__fmul_rn(0.5f, bh)), 0.f), 1024.f);
        float b1 = fminf(fmaxf(__fadd_rn(cx, -__fmul_rn(0.5f, bw)), 0.f), 1024.f);
        float b2 = fminf(fmaxf(__fadd_rn(cy,  __fmul_rn(0.5f, bh)), 0.f), 1024.f);
        float b3 = fminf(fmaxf(__fadd_rn(cx,  __fmul_rn(0.5f, bw)), 0.f), 1024.f);

        float s0 = acc[12 + a * 2], s1 = acc[12 + a * 2 + 1];
        float m  = fmaxf(s0, s1);
        float e0 = expf(__fadd_rn(s0, -m));
        float e1 = expf(__fadd_rn(s1, -m));
        float fg = __fdiv_rn(e1, __fadd_rn(e0, e1));

        float hh = __fadd_rn(b2, -b0);
        float ww2 = __fadd_rn(b3, -b1);
        float scv = (hh >= 16.f && ww2 >= 16.f) ? fg : NEGV;

        int aid = pix * 3 + a;
        g_boxes[aid]  = make_float4(b0, b1, b2, b3);
        g_scores[aid] = scv;
    }
}

// ---------------- exact top-6000 via 4-pass radix select ----------------
__device__ __forceinline__ unsigned int fkey(float f) {
    unsigned int u = __float_as_uint(f);
    return u ^ ((u & 0x80000000u) ? 0xFFFFFFFFu : 0x80000000u);   // monotonic key
}

__global__ void topk_init() {
    int t = threadIdx.x;
    if (t < 256) g_hist[t] = 0;
    if (t == 0) { g_prefix = 0; g_above = 0; g_remain = PRE_NMS_N; g_ctr = 0; g_tiectr = 0; }
}

__global__ void topk_hist(int shift, unsigned int mask) {
    __shared__ unsigned int sh[256];
    if (threadIdx.x < 256) sh[threadIdx.x] = 0;
    __syncthreads();
    unsigned int pref = g_prefix;
    for (int i = blockIdx.x * blockDim.x + threadIdx.x; i < NANCH; i += gridDim.x * blockDim.x) {
        unsigned int k = fkey(g_scores[i]);
        if ((k & mask) == (pref & mask)) atomicAdd(&sh[(k >> shift) & 255u], 1u);
    }
    __syncthreads();
    if (threadIdx.x < 256 && sh[threadIdx.x]) atomicAdd(&g_hist[threadIdx.x], sh[threadIdx.x]);
}

__global__ void topk_select(int shift) {
    __shared__ unsigned int h[256];
    int t = threadIdx.x;
    h[t] = g_hist[t];
    __syncthreads();
    if (t == 0) {
        unsigned int remain = g_remain;
        unsigned int cum = 0;
        int b = 255;
        for (; b > 0; b--) {
            if (cum + h[b] >= remain) break;
            cum += h[b];
        }
        g_above  = g_above + cum;
        g_remain = remain - cum;
        g_prefix = g_prefix | ((unsigned int)b << shift);
    }
    __syncthreads();
    g_hist[t] = 0;
}

__global__ void topk_compact() {
    unsigned int kt = g_prefix;
    for (int i = blockIdx.x * blockDim.x + threadIdx.x; i < NANCH; i += gridDim.x * blockDim.x) {
        float s = g_scores[i];
        unsigned int k = fkey(s);
        if (k > kt) {
            int p = atomicAdd(&g_ctr, 1);
            g_tb[p] = g_boxes[i];
            g_ts[p] = s;
            g_ti[p] = i;
        } else if (k == kt) {
            int p = atomicAdd(&g_tiectr, 1);
            if (p < TIE_CAP) g_ties[p] = i;
        }
    }
}

// lowest-original-index ties first (matches lax.top_k stability)
__global__ void topk_ties() {
    int need = (int)g_remain;
    int base = (int)g_above;
    int M = g_tiectr;
    if (M > TIE_CAP) M = TIE_CAP;
    for (int i = threadIdx.x; i < M; i += blockDim.x) {
        int idx = g_ties[i];
        int rank = 0;
        for (int j = 0; j < M; j++) rank += (g_ties[j] < idx) ? 1 : 0;
        if (rank < need) {
            int p = base + rank;
            g_tb[p] = g_boxes[idx];
            g_ts[p] = g_scores[idx];
            g_ti[p] = idx;
        }
    }
}

// ---------------- sequential NMS (single persistent block) ----------------
__global__ __launch_bounds__(1024) void nms_kernel(float* __restrict__ out) {
    extern __shared__ char smraw[];
    float4* B = (float4*)smraw;
    float*  S = (float*)(B + PRE_NMS_N);
    int*    O = (int*)(S + PRE_NMS_N);
    __shared__ float rs[32];
    __shared__ int   ro[32];
    __shared__ int   rp[32];
    __shared__ float4 cur;
    __shared__ int curp, curvalid;

    const int t = threadIdx.x;
    for (int i = t; i < PRE_NMS_N; i += 1024) {
        B[i] = g_tb[i];
        S[i] = g_ts[i];
        O[i] = g_ti[i];
    }
    __syncthreads();

    for (int it = 0; it < POST_NMS_N; it++) {
        float bs = -3.0e38f;
        int bo = 0x7fffffff, bp = 0;
        for (int i = t; i < PRE_NMS_N; i += 1024) {
            float s = S[i];
            int o = O[i];
            if (s > bs || (s == bs && o < bo)) { bs = s; bo = o; bp = i; }
        }
#pragma unroll
        for (int d = 16; d > 0; d >>= 1) {
            float os = __shfl_down_sync(0xffffffffu, bs, d);
            int   oo = __shfl_down_sync(0xffffffffu, bo, d);
            int   op = __shfl_down_sync(0xffffffffu, bp, d);
            if (os > bs || (os == bs && oo < bo)) { bs = os; bo = oo; bp = op; }
        }
        if ((t & 31) == 0) { rs[t >> 5] = bs; ro[t >> 5] = bo; rp[t >> 5] = bp; }
        __syncthreads();
        if (t == 0) {
            bs = rs[0]; bo = ro[0]; bp = rp[0];
            for (int wi = 1; wi < 32; wi++) {
                if (rs[wi] > bs || (rs[wi] == bs && ro[wi] < bo)) { bs = rs[wi]; bo = ro[wi]; bp = rp[wi]; }
            }
            int valid = (bs > NEGV * 0.5f) ? 1 : 0;
            cur = B[bp];
            curp = bp;
            curvalid = valid;
            float4 ob = valid ? B[bp] : make_float4(0.f, 0.f, 0.f, 0.f);
            out[it * 4 + 0] = ob.x;
            out[it * 4 + 1] = ob.y;
            out[it * 4 + 2] = ob.z;
            out[it * 4 + 3] = ob.w;
        }
        __syncthreads();
        if (curvalid) {
            float4 bb = cur;
            int pi = curp;
            float a1 = __fmul_rn(__fadd_rn(bb.z, -bb.x), __fadd_rn(bb.w, -bb.y));
            for (int i = t; i < PRE_NMS_N; i += 1024) {
                float4 c = B[i];
                float ty = fmaxf(bb.x, c.x);
                float tx = fmaxf(bb.y, c.y);
                float by = fminf(bb.z, c.z);
                float bx = fminf(bb.w, c.w);
                float inter = __fmul_rn(fmaxf(__fadd_rn(by, -ty), 0.f), fmaxf(__fadd_rn(bx, -tx), 0.f));
                float a2 = __fmul_rn(__fadd_rn(c.z, -c.x), __fadd_rn(c.w, -c.y));
                float iou = __fdiv_rn(inter, fmaxf(__fadd_rn(__fadd_rn(a1, a2), -inter), 1e-9f));
                if (iou > 0.7f || i == pi) S[i] = NEGV;
            }
        }
        __syncthreads();
    }
}

// ---------------- host launcher ----------------
extern "C" void kernel_launch(void* const* d_in, const int* in_sizes, int n_in,
                              void* d_out, int out_size)
{
    (void)in_sizes; (void)n_in; (void)out_size;
    const float* p2 = (const float*)d_in[0];
    const float* p3 = (const float*)d_in[1];
    const float* p4 = (const float*)d_in[2];
    const float* p5 = (const float*)d_in[3];
    const float* p6 = (const float*)d_in[4];
    const float* conv_w  = (const float*)d_in[5];
    const float* conv_b  = (const float*)d_in[6];
    const float* loc_w   = (const float*)d_in[7];
    const float* loc_b   = (const float*)d_in[8];
    const float* score_w = (const float*)d_in[9];
    const float* score_b = (const float*)d_in[10];
    float* out = (float*)d_out;

    conv3x3_relu<256><<<dim3(256, 4), 256>>>(p2, conv_w, conv_b, 0);
    conv3x3_relu<128><<<dim3(64, 4),  256>>>(p3, conv_w, conv_b, 65536);
    conv3x3_relu<64> <<<dim3(16, 4),  256>>>(p4, conv_w, conv_b, 81920);
    conv3x3_relu<32> <<<dim3(4, 4),   256>>>(p5, conv_w, conv_b, 86016);
    conv3x3_relu<16> <<<dim3(1, 4),   256>>>(p6, conv_w, conv_b, 87040);

    heads_decode<<<682, 128>>>(loc_w, loc_b, score_w, score_b);

    topk_init<<<1, 256>>>();
    const int shifts[4] = {24, 16, 8, 0};
    const unsigned int masks[4] = {0x00000000u, 0xFF000000u, 0xFFFF0000u, 0xFFFFFF00u};
    for (int p = 0; p < 4; p++) {
        topk_hist<<<512, 256>>>(shifts[p], masks[p]);
        topk_select<<<1, 256>>>(shifts[p]);
    }
    topk_compact<<<512, 256>>>();
    topk_ties<<<1, 1024>>>();

    static const size_t nms_smem = PRE_NMS_N * (sizeof(float4) + sizeof(float) + sizeof(int));
    cudaFuncSetAttribute(nms_kernel, cudaFuncAttributeMaxDynamicSharedMemorySize, (int)nms_smem);
    nms_kernel<<<1, 1024, nms_smem>>>(out);
}

// round 2
// speedup vs baseline: 1.1386x; 1.1386x over previous
#include <cuda_runtime.h>
#include <math.h>

#define HTOT 87296
#define NANCH 261888
#define PRE_NMS_N 6000
#define POST_NMS_N 300
#define NEGV -1000000000.0f
#define TIE_CAP 16384

typedef unsigned long long u64;

// ---------------- device scratch ----------------
static __device__ __align__(16) float g_h[(size_t)256 * HTOT];
static __device__ float4 g_boxes[NANCH];
static __device__ float  g_scores[NANCH];
static __device__ float4 g_tb[PRE_NMS_N];
static __device__ float  g_ts[PRE_NMS_N];
static __device__ int    g_ti[PRE_NMS_N];
static __device__ unsigned int g_hist[256];
static __device__ unsigned int g_prefix, g_above, g_remain;
static __device__ int g_ctr, g_tiectr;
static __device__ int g_ties[TIE_CAP];

// ---------------- f32x2 helpers ----------------
__device__ __forceinline__ void ffma2(u64& d, u64 a, u64 b) {
    asm("fma.rn.f32x2 %0, %1, %2, %0;" : "+l"(d) : "l"(a), "l"(b));
}
__device__ __forceinline__ void unpk(float& lo, float& hi, u64 v) {
    asm("mov.b64 {%0,%1}, %2;" : "=f"(lo), "=f"(hi) : "l"(v));
}

// ---------------- unified conv3x3+relu, all levels, f32x2 ----------------
// Block = 64 oc x 256 pixels x 256 ic. Thread = 4oc x 16pix, accums as oc-pairs.
// Input tile stored DUPLICATED (float2(v,v)) in smem so broadcast pairs are
// plain LDS; weight pairs are contiguous oc in smem (natural 8B loads).
template<int W>
__device__ __forceinline__ void conv_level(
    const float* __restrict__ x, const float* __restrict__ w,
    const float* __restrict__ bias, int lvl_off, int pixtile, int ocb, char* sm)
{
    constexpr int H = W;
    constexpr int TH = 256 / W;
    constexpr int XP = W + 4;        // even pitch -> 16B-aligned pair loads
    constexpr int XROWS = TH + 2;

    float2* Xs = (float2*)sm;                                  // [4][XROWS][XP]
    float*  Ws = (float*)(sm + (size_t)4 * XROWS * XP * 8);    // [4][9][64]

    const int t  = threadIdx.x;
    const int r0 = pixtile * TH;
    const int tp = t & 15;
    const int to = t >> 4;

    int pr[4], pc[4];
#pragma unroll
    for (int g = 0; g < 4; g++) {
        int p = tp * 4 + g * 64;
        pr[g] = p / W;
        pc[g] = p % W;
    }

    u64 acc[4][4][2];
#pragma unroll
    for (int g = 0; g < 4; g++)
#pragma unroll
        for (int j = 0; j < 4; j++) { acc[g][j][0] = 0ull; acc[g][j][1] = 0ull; }

    const int wo  = t >> 2;
    const int wic = t & 3;

    for (int ic0 = 0; ic0 < 256; ic0 += 4) {
        __syncthreads();
        for (int i = t; i < 4 * XROWS * XP; i += 256) {
            int icc = i / (XROWS * XP);
            int rem = i - icc * (XROWS * XP);
            int ry  = rem / XP;
            int rx  = rem - ry * XP;
            int gy  = r0 + ry - 1;
            int gx  = rx - 1;
            float v = 0.f;
            if (gy >= 0 && gy < H && gx >= 0 && gx < W)
                v = x[(size_t)(ic0 + icc) * (H * W) + gy * W + gx];
            Xs[i] = make_float2(v, v);
        }
        {
            const float* wp = w + (size_t)(ocb + wo) * 2304 + (ic0 + wic) * 9;
#pragma unroll
            for (int tap = 0; tap < 9; tap++) Ws[(wic * 9 + tap) * 64 + wo] = wp[tap];
        }
        __syncthreads();

#pragma unroll
        for (int icc = 0; icc < 4; icc++) {
#pragma unroll
            for (int ky = 0; ky < 3; ky++) {
                u64 wq[3][2];
#pragma unroll
                for (int kx = 0; kx < 3; kx++) {
                    const float* wb = &Ws[(icc * 9 + ky * 3 + kx) * 64 + to * 4];
                    wq[kx][0] = *(const u64*)(wb);
                    wq[kx][1] = *(const u64*)(wb + 2);
                }
#pragma unroll
                for (int g = 0; g < 4; g++) {
                    const double2* xr = (const double2*)(Xs + (size_t)(icc * XROWS + pr[g] + ky) * XP + pc[g]);
                    double2 v0 = xr[0];
                    double2 v1 = xr[1];
                    double2 v2 = xr[2];
                    u64 xq[6];
                    xq[0] = (u64)__double_as_longlong(v0.x);
                    xq[1] = (u64)__double_as_longlong(v0.y);
                    xq[2] = (u64)__double_as_longlong(v1.x);
                    xq[3] = (u64)__double_as_longlong(v1.y);
                    xq[4] = (u64)__double_as_longlong(v2.x);
                    xq[5] = (u64)__double_as_longlong(v2.y);
#pragma unroll
                    for (int kx = 0; kx < 3; kx++) {
#pragma unroll
                        for (int j = 0; j < 4; j++) {
                            ffma2(acc[g][j][0], xq[j + kx], wq[kx][0]);
                            ffma2(acc[g][j][1], xq[j + kx], wq[kx][1]);
                        }
                    }
                }
            }
        }
    }

    // epilogue: unpack pairs, bias+relu, vectorized store
#pragma unroll
    for (int o = 0; o < 4; o++) {
        int oc = ocb + to * 4 + o;
        float bv = bias[oc];
        float* hp = g_h + (size_t)oc * HTOT + lvl_off;
#pragma unroll
        for (int g = 0; g < 4; g++) {
            float4 v;
            float lo, hi;
            unpk(lo, hi, acc[g][0][o >> 1]); v.x = (o & 1) ? hi : lo;
            unpk(lo, hi, acc[g][1][o >> 1]); v.y = (o & 1) ? hi : lo;
            unpk(lo, hi, acc[g][2][o >> 1]); v.z = (o & 1) ? hi : lo;
            unpk(lo, hi, acc[g][3][o >> 1]); v.w = (o & 1) ? hi : lo;
            v.x = fmaxf(v.x + bv, 0.f);
            v.y = fmaxf(v.y + bv, 0.f);
            v.z = fmaxf(v.z + bv, 0.f);
            v.w = fmaxf(v.w + bv, 0.f);
            *(float4*)(hp + (r0 + pr[g]) * W + pc[g]) = v;
        }
    }
}

__global__ __launch_bounds__(256, 2) void conv_all(
    const float* __restrict__ p2, const float* __restrict__ p3,
    const float* __restrict__ p4, const float* __restrict__ p5,
    const float* __restrict__ p6, const float* __restrict__ w,
    const float* __restrict__ b)
{
    extern __shared__ char sm[];
    int bid = blockIdx.x;
    if (bid < 1024) {
        conv_level<256>(p2, w, b, 0, bid >> 2, (bid & 3) * 64, sm);
    } else if (bid < 1280) {
        int i = bid - 1024;
        conv_level<128>(p3, w, b, 65536, i >> 2, (i & 3) * 64, sm);
    } else if (bid < 1344) {
        int i = bid - 1280;
        conv_level<64>(p4, w, b, 81920, i >> 2, (i & 3) * 64, sm);
    } else if (bid < 1360) {
        int i = bid - 1344;
        conv_level<32>(p5, w, b, 86016, i >> 2, (i & 3) * 64, sm);
    } else {
        int i = bid - 1360;
        conv_level<16>(p6, w, b, 87040, i >> 2, (i & 3) * 64, sm);
    }
}

#define CONV_SMEM (4 * 3 * 260 * 8 + 4 * 9 * 64 * 4)   // level-256 is max: 34176 B

// ---------------- heads: 1x1 convs + softmax + decode + min-size ----------------
__global__ __launch_bounds__(128) void heads_decode(
    const float* __restrict__ lw, const float* __restrict__ lb,
    const float* __restrict__ sw, const float* __restrict__ sb)
{
    __shared__ float WL[12][256];
    __shared__ float WS[6][256];
    __shared__ float BL[12], BS[6];
    const int t = threadIdx.x;
    for (int i = t; i < 12 * 256; i += 128) WL[i >> 8][i & 255] = lw[i];
    for (int i = t; i < 6 * 256; i += 128)  WS[i >> 8][i & 255] = sw[i];
    if (t < 12) BL[t] = lb[t];
    if (t < 6)  BS[t] = sb[t];
    __syncthreads();

    const int pix = blockIdx.x * 128 + t;
    int lvl;
    if (pix < 65536) lvl = 0;
    else if (pix < 81920) lvl = 1;
    else if (pix < 86016) lvl = 2;
    else if (pix < 87040) lvl = 3;
    else lvl = 4;
    const int offs[5] = {0, 65536, 81920, 86016, 87040};
    const int lp   = pix - offs[lvl];
    const int lw2  = 8 - lvl;
    const int row  = lp >> lw2;
    const int col  = lp & ((1 << lw2) - 1);
    const int strd = 4 << lvl;

    float acc[18];
#pragma unroll
    for (int j = 0; j < 12; j++) acc[j] = BL[j];
#pragma unroll
    for (int j = 0; j < 6; j++)  acc[12 + j] = BS[j];

    const float* hp = g_h + pix;
#pragma unroll 4
    for (int ic = 0; ic < 256; ic++) {
        float v = hp[(size_t)ic * HTOT];
#pragma unroll
        for (int j = 0; j < 12; j++) acc[j] = fmaf(WL[j][ic], v, acc[j]);
#pragma unroll
        for (int j = 0; j < 6; j++)  acc[12 + j] = fmaf(WS[j][ic], v, acc[12 + j]);
    }

    const float y  = (float)(row * strd);
    const float xx = (float)(col * strd);
    const float sr[3] = {0.70710678118654752f, 1.0f, 1.41421356237309505f};
#pragma unroll
    for (int a = 0; a < 3; a++) {
        float hs = (float)(strd * 8) * sr[a];
        float ws = (float)(strd * 8) * sr[2 - a];
        float a0 = __fadd_rn(y,  -0.5f * hs);
        float a1 = __fadd_rn(xx, -0.5f * ws);
        float a2 = __fadd_rn(y,   0.5f * hs);
        float a3 = __fadd_rn(xx,  0.5f * ws);
        float ah = __fadd_rn(a2, -a0);
        float aw = __fadd_rn(a3, -a1);
        float acy = __fadd_rn(a0, __fmul_rn(0.5f, ah));
        float acx = __fadd_rn(a1, __fmul_rn(0.5f, aw));
        float dy = acc[a * 4 + 0], dx = acc[a * 4 + 1];
        float dh = acc[a * 4 + 2], dw = acc[a * 4 + 3];
        float cy = __fadd_rn(__fmul_rn(dy, ah), acy);
        float cx = __fadd_rn(__fmul_rn(dx, aw), acx);
        float bh = __fmul_rn(expf(dh), ah);
        float bw = __fmul_rn(expf(dw), aw);
        float b0 = fminf(fmaxf(__fadd_rn(cy, -__fmul_rn(0.5f, bh)), 0.f), 1024.f);
        float b1 = fminf(fmaxf(__fadd_rn(cx, -__fmul_rn(0.5f, bw)), 0.f), 1024.f);
        float b2 = fminf(fmaxf(__fadd_rn(cy,  __fmul_rn(0.5f, bh)), 0.f), 1024.f);
        float b3 = fminf(fmaxf(__fadd_rn(cx,  __fmul_rn(0.5f, bw)), 0.f), 1024.f);

        float s0 = acc[12 + a * 2], s1 = acc[12 + a * 2 + 1];
        float m  = fmaxf(s0, s1);
        float e0 = expf(__fadd_rn(s0, -m));
        float e1 = expf(__fadd_rn(s1, -m));
        float fg = __fdiv_rn(e1, __fadd_rn(e0, e1));

        float hh  = __fadd_rn(b2, -b0);
        float ww2 = __fadd_rn(b3, -b1);
        float scv = (hh >= 16.f && ww2 >= 16.f) ? fg : NEGV;

        int aid = pix * 3 + a;
        g_boxes[aid]  = make_float4(b0, b1, b2, b3);
        g_scores[aid] = scv;
    }
}

// ---------------- exact top-6000 via 4-pass radix select ----------------
__device__ __forceinline__ unsigned int fkey(float f) {
    unsigned int u = __float_as_uint(f);
    return u ^ ((u & 0x80000000u) ? 0xFFFFFFFFu : 0x80000000u);
}

__global__ void topk_init() {
    int t = threadIdx.x;
    if (t < 256) g_hist[t] = 0;
    if (t == 0) { g_prefix = 0; g_above = 0; g_remain = PRE_NMS_N; g_ctr = 0; g_tiectr = 0; }
}

__global__ void topk_hist(int shift, unsigned int mask) {
    __shared__ unsigned int sh[256];
    if (threadIdx.x < 256) sh[threadIdx.x] = 0;
    __syncthreads();
    unsigned int pref = g_prefix;
    for (int i = blockIdx.x * blockDim.x + threadIdx.x; i < NANCH; i += gridDim.x * blockDim.x) {
        unsigned int k = fkey(g_scores[i]);
        if ((k & mask) == (pref & mask)) atomicAdd(&sh[(k >> shift) & 255u], 1u);
    }
    __syncthreads();
    if (threadIdx.x < 256 && sh[threadIdx.x]) atomicAdd(&g_hist[threadIdx.x], sh[threadIdx.x]);
}

__global__ void topk_select(int shift) {
    __shared__ unsigned int h[256];
    int t = threadIdx.x;
    h[t] = g_hist[t];
    __syncthreads();
    if (t == 0) {
        unsigned int remain = g_remain;
        unsigned int cum = 0;
        int b = 255;
        for (; b > 0; b--) {
            if (cum + h[b] >= remain) break;
            cum += h[b];
        }
        g_above  = g_above + cum;
        g_remain = remain - cum;
        g_prefix = g_prefix | ((unsigned int)b << shift);
    }
    __syncthreads();
    g_hist[t] = 0;
}

__global__ void topk_compact() {
    unsigned int kt = g_prefix;
    for (int i = blockIdx.x * blockDim.x + threadIdx.x; i < NANCH; i += gridDim.x * blockDim.x) {
        float s = g_scores[i];
        unsigned int k = fkey(s);
        if (k > kt) {
            int p = atomicAdd(&g_ctr, 1);
            g_tb[p] = g_boxes[i];
            g_ts[p] = s;
            g_ti[p] = i;
        } else if (k == kt) {
            int p = atomicAdd(&g_tiectr, 1);
            if (p < TIE_CAP) g_ties[p] = i;
        }
    }
}

__global__ void topk_ties() {
    int need = (int)g_remain;
    int base = (int)g_above;
    int M = g_tiectr;
    if (M > TIE_CAP) M = TIE_CAP;
    for (int i = threadIdx.x; i < M; i += blockDim.x) {
        int idx = g_ties[i];
        int rank = 0;
        for (int j = 0; j < M; j++) rank += (g_ties[j] < idx) ? 1 : 0;
        if (rank < need) {
            int p = base + rank;
            g_tb[p] = g_boxes[idx];
            g_ts[p] = g_scores[idx];
            g_ti[p] = idx;
        }
    }
}

// ---------------- sequential NMS (single persistent block) ----------------
__global__ __launch_bounds__(1024) void nms_kernel(float* __restrict__ out) {
    extern __shared__ char smraw[];
    float4* B = (float4*)smraw;
    float*  S = (float*)(B + PRE_NMS_N);
    int*    O = (int*)(S + PRE_NMS_N);
    __shared__ float rs[32];
    __shared__ int   ro[32];
    __shared__ int   rp[32];
    __shared__ float4 cur;
    __shared__ int curp, curvalid;

    const int t = threadIdx.x;
    for (int i = t; i < PRE_NMS_N; i += 1024) {
        B[i] = g_tb[i];
        S[i] = g_ts[i];
        O[i] = g_ti[i];
    }
    __syncthreads();

    for (int it = 0; it < POST_NMS_N; it++) {
        float bs = -3.0e38f;
        int bo = 0x7fffffff, bp = 0;
        for (int i = t; i < PRE_NMS_N; i += 1024) {
            float s = S[i];
            int o = O[i];
            if (s > bs || (s == bs && o < bo)) { bs = s; bo = o; bp = i; }
        }
#pragma unroll
        for (int d = 16; d > 0; d >>= 1) {
            float os = __shfl_down_sync(0xffffffffu, bs, d);
            int   oo = __shfl_down_sync(0xffffffffu, bo, d);
            int   op = __shfl_down_sync(0xffffffffu, bp, d);
            if (os > bs || (os == bs && oo < bo)) { bs = os; bo = oo; bp = op; }
        }
        if ((t & 31) == 0) { rs[t >> 5] = bs; ro[t >> 5] = bo; rp[t >> 5] = bp; }
        __syncthreads();
        if (t < 32) {
            bs = rs[t]; bo = ro[t]; bp = rp[t];
#pragma unroll
            for (int d = 16; d > 0; d >>= 1) {
                float os = __shfl_down_sync(0xffffffffu, bs, d);
                int   oo = __shfl_down_sync(0xffffffffu, bo, d);
                int   op = __shfl_down_sync(0xffffffffu, bp, d);
                if (os > bs || (os == bs && oo < bo)) { bs = os; bo = oo; bp = op; }
            }
            if (t == 0) {
                int valid = (bs > NEGV * 0.5f) ? 1 : 0;
                cur = B[bp];
                curp = bp;
                curvalid = valid;
                float4 ob = valid ? B[bp] : make_float4(0.f, 0.f, 0.f, 0.f);
                out[it * 4 + 0] = ob.x;
                out[it * 4 + 1] = ob.y;
                out[it * 4 + 2] = ob.z;
                out[it * 4 + 3] = ob.w;
            }
        }
        __syncthreads();
        if (curvalid) {
            float4 bb = cur;
            int pi = curp;
            float a1 = __fmul_rn(__fadd_rn(bb.z, -bb.x), __fadd_rn(bb.w, -bb.y));
            for (int i = t; i < PRE_NMS_N; i += 1024) {
                float4 c = B[i];
                float ty = fmaxf(bb.x, c.x);
                float tx = fmaxf(bb.y, c.y);
                float by = fminf(bb.z, c.z);
                float bx = fminf(bb.w, c.w);
                float inter = __fmul_rn(fmaxf(__fadd_rn(by, -ty), 0.f), fmaxf(__fadd_rn(bx, -tx), 0.f));
                float a2 = __fmul_rn(__fadd_rn(c.z, -c.x), __fadd_rn(c.w, -c.y));
                float iou = __fdiv_rn(inter, fmaxf(__fadd_rn(__fadd_rn(a1, a2), -inter), 1e-9f));
                if (iou > 0.7f || i == pi) S[i] = NEGV;
            }
        }
        __syncthreads();
    }
}

// ---------------- host launcher ----------------
extern "C" void kernel_launch(void* const* d_in, const int* in_sizes, int n_in,
                              void* d_out, int out_size)
{
    (void)in_sizes; (void)n_in; (void)out_size;
    const float* p2 = (const float*)d_in[0];
    const float* p3 = (const float*)d_in[1];
    const float* p4 = (const float*)d_in[2];
    const float* p5 = (const float*)d_in[3];
    const float* p6 = (const float*)d_in[4];
    const float* conv_w  = (const float*)d_in[5];
    const float* conv_b  = (const float*)d_in[6];
    const float* loc_w   = (const float*)d_in[7];
    const float* loc_b   = (const float*)d_in[8];
    const float* score_w = (const float*)d_in[9];
    const float* score_b = (const float*)d_in[10];
    float* out = (float*)d_out;

    static int init_done = 0;
    if (!init_done) {
        cudaFuncSetAttribute(conv_all, cudaFuncAttributeMaxDynamicSharedMemorySize, CONV_SMEM);
        size_t nms_smem = PRE_NMS_N * (sizeof(float4) + sizeof(float) + sizeof(int));
        cudaFuncSetAttribute(nms_kernel, cudaFuncAttributeMaxDynamicSharedMemorySize, (int)nms_smem);
        init_done = 1;
    }

    conv_all<<<1364, 256, CONV_SMEM>>>(p2, p3, p4, p5, p6, conv_w, conv_b);

    heads_decode<<<682, 128>>>(loc_w, loc_b, score_w, score_b);

    topk_init<<<1, 256>>>();
    const int shifts[4] = {24, 16, 8, 0};
    const unsigned int masks[4] = {0x00000000u, 0xFF000000u, 0xFFFF0000u, 0xFFFFFF00u};
    for (int p = 0; p < 4; p++) {
        topk_hist<<<512, 256>>>(shifts[p], masks[p]);
        topk_select<<<1, 256>>>(shifts[p]);
    }
    topk_compact<<<512, 256>>>();
    topk_ties<<<1, 1024>>>();

    size_t nms_smem = PRE_NMS_N * (sizeof(float4) + sizeof(float) + sizeof(int));
    nms_kernel<<<1, 1024, nms_smem>>>(out);
}

// round 3
// speedup vs baseline: 1.5021x; 1.3193x over previous
#include <cuda_runtime.h>
#include <math.h>

#define HTOT 87296
#define NANCH 261888
#define PRE_NMS_N 6000
#define POST_NMS_N 300
#define NEGV -1000000000.0f
#define TIE_CAP 16384

typedef unsigned long long u64;

// ---------------- device scratch ----------------
static __device__ __align__(16) float g_h[(size_t)256 * HTOT];
static __device__ float4 g_boxes[NANCH];
static __device__ float  g_scores[NANCH];
static __device__ float4 g_tb[PRE_NMS_N];
static __device__ float  g_ts[PRE_NMS_N];
static __device__ int    g_ti[PRE_NMS_N];
static __device__ unsigned int g_hist[256];
static __device__ unsigned int g_prefix, g_above, g_remain;
static __device__ int g_ctr, g_tiectr;
static __device__ int g_ties[TIE_CAP];

// ---------------- f32x2 helpers ----------------
__device__ __forceinline__ void ffma2(u64& d, u64 a, u64 b) {
    asm("fma.rn.f32x2 %0, %1, %2, %0;" : "+l"(d) : "l"(a), "l"(b));
}
__device__ __forceinline__ void unpk(float& lo, float& hi, u64 v) {
    asm("mov.b64 {%0,%1}, %2;" : "=f"(lo), "=f"(hi) : "l"(v));
}
__device__ __forceinline__ u64 dup2(float v) {
    u64 r;
    asm("mov.b64 %0, {%1, %2};" : "=l"(r) : "f"(v), "f"(v));
    return r;
}

// ---------------- unified conv3x3+relu, all levels, f32x2 ----------------
// Block = 64 oc x 256 pixels x 256 ic. Thread = 4oc(2 pairs) x 16pix.
// x stored as plain floats in smem (no duplication); broadcast pairs built
// in registers via mov.b64 {v,v} (ALU pipe). Weight pairs contiguous in smem.
template<int W>
__device__ __forceinline__ void conv_level(
    const float* __restrict__ x, const float* __restrict__ w,
    const float* __restrict__ bias, int lvl_off, int pixtile, int ocb, char* sm)
{
    constexpr int H = W;
    constexpr int TH = 256 / W;
    constexpr int XP = W + 4;        // float pitch; XP*4B multiple of 16 for all W
    constexpr int XROWS = TH + 2;

    float* Xs = (float*)sm;                                    // [4][XROWS][XP]
    float* Ws = (float*)(sm + (size_t)4 * XROWS * XP * 4);     // [4][9][64]

    const int t  = threadIdx.x;
    const int r0 = pixtile * TH;
    const int tp = t & 15;
    const int to = t >> 4;

    int pr[4], pc[4];
#pragma unroll
    for (int g = 0; g < 4; g++) {
        int p = tp * 4 + g * 64;
        pr[g] = p / W;
        pc[g] = p % W;
    }

    u64 acc[4][4][2];
#pragma unroll
    for (int g = 0; g < 4; g++)
#pragma unroll
        for (int j = 0; j < 4; j++) { acc[g][j][0] = 0ull; acc[g][j][1] = 0ull; }

    const int wo  = t >> 2;
    const int wic = t & 3;

    for (int ic0 = 0; ic0 < 256; ic0 += 4) {
        __syncthreads();
        for (int i = t; i < 4 * XROWS * XP; i += 256) {
            int icc = i / (XROWS * XP);
            int rem = i - icc * (XROWS * XP);
            int ry  = rem / XP;
            int rx  = rem - ry * XP;
            int gy  = r0 + ry - 1;
            int gx  = rx - 1;
            float v = 0.f;
            if (gy >= 0 && gy < H && gx >= 0 && gx < W)
                v = x[(size_t)(ic0 + icc) * (H * W) + gy * W + gx];
            Xs[i] = v;
        }
        {
            const float* wp = w + (size_t)(ocb + wo) * 2304 + (ic0 + wic) * 9;
#pragma unroll
            for (int tap = 0; tap < 9; tap++) Ws[(wic * 9 + tap) * 64 + wo] = wp[tap];
        }
        __syncthreads();

#pragma unroll
        for (int icc = 0; icc < 4; icc++) {
#pragma unroll
            for (int ky = 0; ky < 3; ky++) {
                u64 wq[3][2];
#pragma unroll
                for (int kx = 0; kx < 3; kx++) {
                    const float* wb = &Ws[(icc * 9 + ky * 3 + kx) * 64 + to * 4];
                    wq[kx][0] = *(const u64*)(wb);
                    wq[kx][1] = *(const u64*)(wb + 2);
                }
#pragma unroll
                for (int g = 0; g < 4; g++) {
                    const float* xr = Xs + (size_t)(icc * XROWS + pr[g] + ky) * XP + pc[g];
                    float4 xa = *(const float4*)xr;          // x0..x3 (16B aligned)
                    float2 xb = *(const float2*)(xr + 4);    // x4..x5 (8B aligned)
                    u64 xq[6];
                    xq[0] = dup2(xa.x);
                    xq[1] = dup2(xa.y);
                    xq[2] = dup2(xa.z);
                    xq[3] = dup2(xa.w);
                    xq[4] = dup2(xb.x);
                    xq[5] = dup2(xb.y);
#pragma unroll
                    for (int kx = 0; kx < 3; kx++) {
#pragma unroll
                        for (int j = 0; j < 4; j++) {
                            ffma2(acc[g][j][0], xq[j + kx], wq[kx][0]);
                            ffma2(acc[g][j][1], xq[j + kx], wq[kx][1]);
                        }
                    }
                }
            }
        }
    }

    // epilogue: unpack pairs, bias+relu, vectorized store
#pragma unroll
    for (int o = 0; o < 4; o++) {
        int oc = ocb + to * 4 + o;
        float bv = bias[oc];
        float* hp = g_h + (size_t)oc * HTOT + lvl_off;
#pragma unroll
        for (int g = 0; g < 4; g++) {
            float4 v;
            float lo, hi;
            unpk(lo, hi, acc[g][0][o >> 1]); v.x = (o & 1) ? hi : lo;
            unpk(lo, hi, acc[g][1][o >> 1]); v.y = (o & 1) ? hi : lo;
            unpk(lo, hi, acc[g][2][o >> 1]); v.z = (o & 1) ? hi : lo;
            unpk(lo, hi, acc[g][3][o >> 1]); v.w = (o & 1) ? hi : lo;
            v.x = fmaxf(v.x + bv, 0.f);
            v.y = fmaxf(v.y + bv, 0.f);
            v.z = fmaxf(v.z + bv, 0.f);
            v.w = fmaxf(v.w + bv, 0.f);
            *(float4*)(hp + (r0 + pr[g]) * W + pc[g]) = v;
        }
    }
}

__global__ __launch_bounds__(256, 2) void conv_all(
    const float* __restrict__ p2, const float* __restrict__ p3,
    const float* __restrict__ p4, const float* __restrict__ p5,
    const float* __restrict__ p6, const float* __restrict__ w,
    const float* __restrict__ b)
{
    extern __shared__ char sm[];
    int bid = blockIdx.x;
    if (bid < 1024) {
        conv_level<256>(p2, w, b, 0, bid >> 2, (bid & 3) * 64, sm);
    } else if (bid < 1280) {
        int i = bid - 1024;
        conv_level<128>(p3, w, b, 65536, i >> 2, (i & 3) * 64, sm);
    } else if (bid < 1344) {
        int i = bid - 1280;
        conv_level<64>(p4, w, b, 81920, i >> 2, (i & 3) * 64, sm);
    } else if (bid < 1360) {
        int i = bid - 1344;
        conv_level<32>(p5, w, b, 86016, i >> 2, (i & 3) * 64, sm);
    } else {
        int i = bid - 1360;
        conv_level<16>(p6, w, b, 87040, i >> 2, (i & 3) * 64, sm);
    }
}

// level-256 is max: 4*3*260*4 (x tile) + 4*9*64*4 (weights) = 12480 + 9216
#define CONV_SMEM (4 * 3 * 260 * 4 + 4 * 9 * 64 * 4)

// ---------------- heads: 1x1 convs + softmax + decode + min-size ----------------
__global__ __launch_bounds__(128) void heads_decode(
    const float* __restrict__ lw, const float* __restrict__ lb,
    const float* __restrict__ sw, const float* __restrict__ sb)
{
    __shared__ float WL[12][256];
    __shared__ float WS[6][256];
    __shared__ float BL[12], BS[6];
    const int t = threadIdx.x;
    for (int i = t; i < 12 * 256; i += 128) WL[i >> 8][i & 255] = lw[i];
    for (int i = t; i < 6 * 256; i += 128)  WS[i >> 8][i & 255] = sw[i];
    if (t < 12) BL[t] = lb[t];
    if (t < 6)  BS[t] = sb[t];
    __syncthreads();

    const int pix = blockIdx.x * 128 + t;
    int lvl;
    if (pix < 65536) lvl = 0;
    else if (pix < 81920) lvl = 1;
    else if (pix < 86016) lvl = 2;
    else if (pix < 87040) lvl = 3;
    else lvl = 4;
    const int offs[5] = {0, 65536, 81920, 86016, 87040};
    const int lp   = pix - offs[lvl];
    const int lw2  = 8 - lvl;
    const int row  = lp >> lw2;
    const int col  = lp & ((1 << lw2) - 1);
    const int strd = 4 << lvl;

    float acc[18];
#pragma unroll
    for (int j = 0; j < 12; j++) acc[j] = BL[j];
#pragma unroll
    for (int j = 0; j < 6; j++)  acc[12 + j] = BS[j];

    const float* hp = g_h + pix;
#pragma unroll 4
    for (int ic = 0; ic < 256; ic++) {
        float v = hp[(size_t)ic * HTOT];
#pragma unroll
        for (int j = 0; j < 12; j++) acc[j] = fmaf(WL[j][ic], v, acc[j]);
#pragma unroll
        for (int j = 0; j < 6; j++)  acc[12 + j] = fmaf(WS[j][ic], v, acc[12 + j]);
    }

    const float y  = (float)(row * strd);
    const float xx = (float)(col * strd);
    const float sr[3] = {0.70710678118654752f, 1.0f, 1.41421356237309505f};
#pragma unroll
    for (int a = 0; a < 3; a++) {
        float hs = (float)(strd * 8) * sr[a];
        float ws = (float)(strd * 8) * sr[2 - a];
        float a0 = __fadd_rn(y,  -0.5f * hs);
        float a1 = __fadd_rn(xx, -0.5f * ws);
        float a2 = __fadd_rn(y,   0.5f * hs);
        float a3 = __fadd_rn(xx,  0.5f * ws);
        float ah = __fadd_rn(a2, -a0);
        float aw = __fadd_rn(a3, -a1);
        float acy = __fadd_rn(a0, __fmul_rn(0.5f, ah));
        float acx = __fadd_rn(a1, __fmul_rn(0.5f, aw));
        float dy = acc[a * 4 + 0], dx = acc[a * 4 + 1];
        float dh = acc[a * 4 + 2], dw = acc[a * 4 + 3];
        float cy = __fadd_rn(__fmul_rn(dy, ah), acy);
        float cx = __fadd_rn(__fmul_rn(dx, aw), acx);
        float bh = __fmul_rn(expf(dh), ah);
        float bw = __fmul_rn(expf(dw), aw);
        float b0 = fminf(fmaxf(__fadd_rn(cy, -__fmul_rn(0.5f, bh)), 0.f), 1024.f);
        float b1 = fminf(fmaxf(__fadd_rn(cx, -__fmul_rn(0.5f, bw)), 0.f), 1024.f);
        float b2 = fminf(fmaxf(__fadd_rn(cy,  __fmul_rn(0.5f, bh)), 0.f), 1024.f);
        float b3 = fminf(fmaxf(__fadd_rn(cx,  __fmul_rn(0.5f, bw)), 0.f), 1024.f);

        float s0 = acc[12 + a * 2], s1 = acc[12 + a * 2 + 1];
        float m  = fmaxf(s0, s1);
        float e0 = expf(__fadd_rn(s0, -m));
        float e1 = expf(__fadd_rn(s1, -m));
        float fg = __fdiv_rn(e1, __fadd_rn(e0, e1));

        float hh  = __fadd_rn(b2, -b0);
        float ww2 = __fadd_rn(b3, -b1);
        float scv = (hh >= 16.f && ww2 >= 16.f) ? fg : NEGV;

        int aid = pix * 3 + a;
        g_boxes[aid]  = make_float4(b0, b1, b2, b3);
        g_scores[aid] = scv;
    }
}

// ---------------- exact top-6000 via 4-pass radix select ----------------
__device__ __forceinline__ unsigned int fkey(float f) {
    unsigned int u = __float_as_uint(f);
    return u ^ ((u & 0x80000000u) ? 0xFFFFFFFFu : 0x80000000u);
}

__global__ void topk_init() {
    int t = threadIdx.x;
    if (t < 256) g_hist[t] = 0;
    if (t == 0) { g_prefix = 0; g_above = 0; g_remain = PRE_NMS_N; g_ctr = 0; g_tiectr = 0; }
}

__global__ void topk_hist(int shift, unsigned int mask) {
    __shared__ unsigned int sh[256];
    if (threadIdx.x < 256) sh[threadIdx.x] = 0;
    __syncthreads();
    unsigned int pref = g_prefix;
    for (int i = blockIdx.x * blockDim.x + threadIdx.x; i < NANCH; i += gridDim.x * blockDim.x) {
        unsigned int k = fkey(g_scores[i]);
        if ((k & mask) == (pref & mask)) atomicAdd(&sh[(k >> shift) & 255u], 1u);
    }
    __syncthreads();
    if (threadIdx.x < 256 && sh[threadIdx.x]) atomicAdd(&g_hist[threadIdx.x], sh[threadIdx.x]);
}

__global__ void topk_select(int shift) {
    __shared__ unsigned int h[256];
    int t = threadIdx.x;
    h[t] = g_hist[t];
    __syncthreads();
    if (t == 0) {
        unsigned int remain = g_remain;
        unsigned int cum = 0;
        int b = 255;
        for (; b > 0; b--) {
            if (cum + h[b] >= remain) break;
            cum += h[b];
        }
        g_above  = g_above + cum;
        g_remain = remain - cum;
        g_prefix = g_prefix | ((unsigned int)b << shift);
    }
    __syncthreads();
    g_hist[t] = 0;
}

__global__ void topk_compact() {
    unsigned int kt = g_prefix;
    for (int i = blockIdx.x * blockDim.x + threadIdx.x; i < NANCH; i += gridDim.x * blockDim.x) {
        float s = g_scores[i];
        unsigned int k = fkey(s);
        if (k > kt) {
            int p = atomicAdd(&g_ctr, 1);
            g_tb[p] = g_boxes[i];
            g_ts[p] = s;
            g_ti[p] = i;
        } else if (k == kt) {
            int p = atomicAdd(&g_tiectr, 1);
            if (p < TIE_CAP) g_ties[p] = i;
        }
    }
}

__global__ void topk_ties() {
    int need = (int)g_remain;
    int base = (int)g_above;
    int M = g_tiectr;
    if (M > TIE_CAP) M = TIE_CAP;
    for (int i = threadIdx.x; i < M; i += blockDim.x) {
        int idx = g_ties[i];
        int rank = 0;
        for (int j = 0; j < M; j++) rank += (g_ties[j] < idx) ? 1 : 0;
        if (rank < need) {
            int p = base + rank;
            g_tb[p] = g_boxes[idx];
            g_ts[p] = g_scores[idx];
            g_ti[p] = idx;
        }
    }
}

// ---------------- sequential NMS (single persistent block) ----------------
__global__ __launch_bounds__(1024) void nms_kernel(float* __restrict__ out) {
    extern __shared__ char smraw[];
    float4* B = (float4*)smraw;
    float*  S = (float*)(B + PRE_NMS_N);
    int*    O = (int*)(S + PRE_NMS_N);
    __shared__ float rs[32];
    __shared__ int   ro[32];
    __shared__ int   rp[32];
    __shared__ float4 cur;
    __shared__ int curp, curvalid;

    const int t = threadIdx.x;
    for (int i = t; i < PRE_NMS_N; i += 1024) {
        B[i] = g_tb[i];
        S[i] = g_ts[i];
        O[i] = g_ti[i];
    }
    __syncthreads();

    for (int it = 0; it < POST_NMS_N; it++) {
        float bs = -3.0e38f;
        int bo = 0x7fffffff, bp = 0;
        for (int i = t; i < PRE_NMS_N; i += 1024) {
            float s = S[i];
            int o = O[i];
            if (s > bs || (s == bs && o < bo)) { bs = s; bo = o; bp = i; }
        }
#pragma unroll
        for (int d = 16; d > 0; d >>= 1) {
            float os = __shfl_down_sync(0xffffffffu, bs, d);
            int   oo = __shfl_down_sync(0xffffffffu, bo, d);
            int   op = __shfl_down_sync(0xffffffffu, bp, d);
            if (os > bs || (os == bs && oo < bo)) { bs = os; bo = oo; bp = op; }
        }
        if ((t & 31) == 0) { rs[t >> 5] = bs; ro[t >> 5] = bo; rp[t >> 5] = bp; }
        __syncthreads();
        if (t < 32) {
            bs = rs[t]; bo = ro[t]; bp = rp[t];
#pragma unroll
            for (int d = 16; d > 0; d >>= 1) {
                float os = __shfl_down_sync(0xffffffffu, bs, d);
                int   oo = __shfl_down_sync(0xffffffffu, bo, d);
                int   op = __shfl_down_sync(0xffffffffu, bp, d);
                if (os > bs || (os == bs && oo < bo)) { bs = os; bo = oo; bp = op; }
            }
            if (t == 0) {
                int valid = (bs > NEGV * 0.5f) ? 1 : 0;
                cur = B[bp];
                curp = bp;
                curvalid = valid;
                float4 ob = valid ? B[bp] : make_float4(0.f, 0.f, 0.f, 0.f);
                out[it * 4 + 0] = ob.x;
                out[it * 4 + 1] = ob.y;
                out[it * 4 + 2] = ob.z;
                out[it * 4 + 3] = ob.w;
            }
        }
        __syncthreads();
        if (curvalid) {
            float4 bb = cur;
            int pi = curp;
            float a1 = __fmul_rn(__fadd_rn(bb.z, -bb.x), __fadd_rn(bb.w, -bb.y));
            for (int i = t; i < PRE_NMS_N; i += 1024) {
                float4 c = B[i];
                float ty = fmaxf(bb.x, c.x);
                float tx = fmaxf(bb.y, c.y);
                float by = fminf(bb.z, c.z);
                float bx = fminf(bb.w, c.w);
                float inter = __fmul_rn(fmaxf(__fadd_rn(by, -ty), 0.f), fmaxf(__fadd_rn(bx, -tx), 0.f));
                float a2 = __fmul_rn(__fadd_rn(c.z, -c.x), __fadd_rn(c.w, -c.y));
                float iou = __fdiv_rn(inter, fmaxf(__fadd_rn(__fadd_rn(a1, a2), -inter), 1e-9f));
                if (iou > 0.7f || i == pi) S[i] = NEGV;
            }
        }
        __syncthreads();
    }
}

// ---------------- host launcher ----------------
extern "C" void kernel_launch(void* const* d_in, const int* in_sizes, int n_in,
                              void* d_out, int out_size)
{
    (void)in_sizes; (void)n_in; (void)out_size;
    const float* p2 = (const float*)d_in[0];
    const float* p3 = (const float*)d_in[1];
    const float* p4 = (const float*)d_in[2];
    const float* p5 = (const float*)d_in[3];
    const float* p6 = (const float*)d_in[4];
    const float* conv_w  = (const float*)d_in[5];
    const float* conv_b  = (const float*)d_in[6];
    const float* loc_w   = (const float*)d_in[7];
    const float* loc_b   = (const float*)d_in[8];
    const float* score_w = (const float*)d_in[9];
    const float* score_b = (const float*)d_in[10];
    float* out = (float*)d_out;

    static int init_done = 0;
    if (!init_done) {
        cudaFuncSetAttribute(conv_all, cudaFuncAttributeMaxDynamicSharedMemorySize, CONV_SMEM);
        size_t nms_smem = PRE_NMS_N * (sizeof(float4) + sizeof(float) + sizeof(int));
        cudaFuncSetAttribute(nms_kernel, cudaFuncAttributeMaxDynamicSharedMemorySize, (int)nms_smem);
        init_done = 1;
    }

    conv_all<<<1364, 256, CONV_SMEM>>>(p2, p3, p4, p5, p6, conv_w, conv_b);

    heads_decode<<<682, 128>>>(loc_w, loc_b, score_w, score_b);

    topk_init<<<1, 256>>>();
    const int shifts[4] = {24, 16, 8, 0};
    const unsigned int masks[4] = {0x00000000u, 0xFF000000u, 0xFFFF0000u, 0xFFFFFF00u};
    for (int p = 0; p < 4; p++) {
        topk_hist<<<512, 256>>>(shifts[p], masks[p]);
        topk_select<<<1, 256>>>(shifts[p]);
    }
    topk_compact<<<512, 256>>>();
    topk_ties<<<1, 1024>>>();

    size_t nms_smem = PRE_NMS_N * (sizeof(float4) + sizeof(float) + sizeof(int));
    nms_kernel<<<1, 1024, nms_smem>>>(out);
}

// round 4
// speedup vs baseline: 1.5237x; 1.0144x over previous
#include <cuda_runtime.h>
#include <math.h>

#define HTOT 87296
#define NANCH 261888
#define PRE_NMS_N 6000
#define POST_NMS_N 300
#define NEGV -1000000000.0f
#define TIE_CAP 16384

typedef unsigned long long u64;

// ---------------- device scratch ----------------
static __device__ __align__(16) float g_h[(size_t)256 * HTOT];
static __device__ float4 g_boxes[NANCH];
static __device__ float  g_scores[NANCH];
static __device__ float4 g_tb[PRE_NMS_N];
static __device__ float  g_ts[PRE_NMS_N];
static __device__ int    g_ti[PRE_NMS_N];
static __device__ unsigned int g_hist[256];
static __device__ unsigned int g_prefix, g_above, g_remain;
static __device__ int g_ctr, g_tiectr;
static __device__ int g_ties[TIE_CAP];

// ---------------- f32x2 helpers ----------------
__device__ __forceinline__ void ffma2(u64& d, u64 a, u64 b) {
    asm("fma.rn.f32x2 %0, %1, %2, %0;" : "+l"(d) : "l"(a), "l"(b));
}
__device__ __forceinline__ void unpk(float& lo, float& hi, u64 v) {
    asm("mov.b64 {%0,%1}, %2;" : "=f"(lo), "=f"(hi) : "l"(v));
}

// ---------------- dummy kernels: position conv_all at ncu capture slot ----
__global__ void dummy_k() {}

// ---------------- unified conv3x3+relu, all levels, f32x2 pixel-pairs -----
// Block = 64 oc x 256 pixels x 256 ic. Thread = 4 oc x 16 pix (8 pixel-pairs).
// x tile: copy A (aligned) + copy B shifted by +3 floats so odd-phase pairs
// (x1,x2),(x3,x4) are one aligned LDS.128. Weights duplicated (w,w) in smem.
// Zero pair-packing MOVs in the inner loop.
template<int W>
__device__ __forceinline__ void conv_level(
    const float* __restrict__ x, const float* __restrict__ w,
    const float* __restrict__ bias, int lvl_off, int pixtile, int ocb, char* sm)
{
    constexpr int H = W;
    constexpr int TH = 256 / W;
    constexpr int XP = W + 4;          // float pitch, multiple of 4
    constexpr int XROWS = TH + 2;
    constexpr int XSZ = 4 * XROWS * XP;

    float* XsA = (float*)sm;                     // [4][XROWS][XP]
    float* XsB = XsA + XSZ;                      // [4][XROWS][XP], B[m] = A[m-3]
    float* Wd  = XsB + XSZ;                      // [4][9][128] duplicated pairs

    const int t  = threadIdx.x;
    const int r0 = pixtile * TH;
    const int tp = t & 15;
    const int to = t >> 4;

    int pr[4], pc[4];
#pragma unroll
    for (int g = 0; g < 4; g++) {
        int p = tp * 4 + g * 64;
        pr[g] = p / W;
        pc[g] = p % W;
    }

    u64 acc[4][2][4];   // [g][pixel-pair jp][oc]
#pragma unroll
    for (int g = 0; g < 4; g++)
#pragma unroll
        for (int jp = 0; jp < 2; jp++)
#pragma unroll
            for (int o = 0; o < 4; o++) acc[g][jp][o] = 0ull;

    const int wo  = t >> 2;
    const int wic = t & 3;

    for (int ic0 = 0; ic0 < 256; ic0 += 4) {
        __syncthreads();
        for (int i = t; i < XSZ; i += 256) {
            int icc = i / (XROWS * XP);
            int rem = i - icc * (XROWS * XP);
            int ry  = rem / XP;
            int rx  = rem - ry * XP;
            int gy  = r0 + ry - 1;
            int gx  = rx - 1;
            float v = 0.f;
            if (gy >= 0 && gy < H && gx >= 0 && gx < W)
                v = x[(size_t)(ic0 + icc) * (H * W) + gy * W + gx];
            XsA[i] = v;
            if (rx <= W) XsB[(icc * XROWS + ry) * XP + rx + 3] = v;
        }
        {
            const float* wp = w + (size_t)(ocb + wo) * 2304 + (ic0 + wic) * 9;
#pragma unroll
            for (int tap = 0; tap < 9; tap++) {
                float v = wp[tap];
                int base = (wic * 9 + tap) * 128 + wo * 2;
                Wd[base]     = v;
                Wd[base + 1] = v;
            }
        }
        __syncthreads();

#pragma unroll
        for (int icc = 0; icc < 4; icc++) {
#pragma unroll
            for (int ky = 0; ky < 3; ky++) {
                u64 wq[3][4];
#pragma unroll
                for (int kx = 0; kx < 3; kx++) {
                    const ulonglong2* wb =
                        (const ulonglong2*)&Wd[(icc * 9 + ky * 3 + kx) * 128 + to * 8];
                    ulonglong2 w01 = wb[0];
                    ulonglong2 w23 = wb[1];
                    wq[kx][0] = w01.x; wq[kx][1] = w01.y;
                    wq[kx][2] = w23.x; wq[kx][3] = w23.y;
                }
#pragma unroll
                for (int g = 0; g < 4; g++) {
                    const int rowoff = (icc * XROWS + pr[g] + ky) * XP + pc[g];
                    ulonglong2 e = *(const ulonglong2*)(XsA + rowoff);   // (x0,x1),(x2,x3)
                    u64 p45      = *(const u64*)(XsA + rowoff + 4);      // (x4,x5)
                    ulonglong2 o2 = *(const ulonglong2*)(XsB + rowoff + 4); // (x1,x2),(x3,x4)
                    // kx = 0
#pragma unroll
                    for (int o = 0; o < 4; o++) {
                        ffma2(acc[g][0][o], e.x, wq[0][o]);
                        ffma2(acc[g][1][o], e.y, wq[0][o]);
                    }
                    // kx = 1
#pragma unroll
                    for (int o = 0; o < 4; o++) {
                        ffma2(acc[g][0][o], o2.x, wq[1][o]);
                        ffma2(acc[g][1][o], o2.y, wq[1][o]);
                    }
                    // kx = 2
#pragma unroll
                    for (int o = 0; o < 4; o++) {
                        ffma2(acc[g][0][o], e.y, wq[2][o]);
                        ffma2(acc[g][1][o], p45, wq[2][o]);
                    }
                }
            }
        }
    }

    // epilogue: unpack pixel-pairs, bias+relu, float4 store
#pragma unroll
    for (int o = 0; o < 4; o++) {
        int oc = ocb + to * 4 + o;
        float bv = bias[oc];
        float* hp = g_h + (size_t)oc * HTOT + lvl_off;
#pragma unroll
        for (int g = 0; g < 4; g++) {
            float4 v;
            float lo, hi;
            unpk(lo, hi, acc[g][0][o]); v.x = lo; v.y = hi;
            unpk(lo, hi, acc[g][1][o]); v.z = lo; v.w = hi;
            v.x = fmaxf(v.x + bv, 0.f);
            v.y = fmaxf(v.y + bv, 0.f);
            v.z = fmaxf(v.z + bv, 0.f);
            v.w = fmaxf(v.w + bv, 0.f);
            *(float4*)(hp + (r0 + pr[g]) * W + pc[g]) = v;
        }
    }
}

__global__ __launch_bounds__(256, 2) void conv_all(
    const float* __restrict__ p2, const float* __restrict__ p3,
    const float* __restrict__ p4, const float* __restrict__ p5,
    const float* __restrict__ p6, const float* __restrict__ w,
    const float* __restrict__ b)
{
    extern __shared__ char sm[];
    int bid = blockIdx.x;
    if (bid < 1024) {
        conv_level<256>(p2, w, b, 0, bid >> 2, (bid & 3) * 64, sm);
    } else if (bid < 1280) {
        int i = bid - 1024;
        conv_level<128>(p3, w, b, 65536, i >> 2, (i & 3) * 64, sm);
    } else if (bid < 1344) {
        int i = bid - 1280;
        conv_level<64>(p4, w, b, 81920, i >> 2, (i & 3) * 64, sm);
    } else if (bid < 1360) {
        int i = bid - 1344;
        conv_level<32>(p5, w, b, 86016, i >> 2, (i & 3) * 64, sm);
    } else {
        int i = bid - 1360;
        conv_level<16>(p6, w, b, 87040, i >> 2, (i & 3) * 64, sm);
    }
}

// max at W=256: 2 * (4*3*260*4) + 4*9*128*4 = 24960 + 18432 = 43392
#define CONV_SMEM (2 * (4 * 3 * 260 * 4) + 4 * 9 * 128 * 4)

// ---------------- heads: 1x1 convs + softmax + decode + min-size ----------------
__global__ __launch_bounds__(128) void heads_decode(
    const float* __restrict__ lw, const float* __restrict__ lb,
    const float* __restrict__ sw, const float* __restrict__ sb)
{
    __shared__ float WL[12][256];
    __shared__ float WS[6][256];
    __shared__ float BL[12], BS[6];
    const int t = threadIdx.x;
    for (int i = t; i < 12 * 256; i += 128) WL[i >> 8][i & 255] = lw[i];
    for (int i = t; i < 6 * 256; i += 128)  WS[i >> 8][i & 255] = sw[i];
    if (t < 12) BL[t] = lb[t];
    if (t < 6)  BS[t] = sb[t];
    __syncthreads();

    const int pix = blockIdx.x * 128 + t;
    int lvl;
    if (pix < 65536) lvl = 0;
    else if (pix < 81920) lvl = 1;
    else if (pix < 86016) lvl = 2;
    else if (pix < 87040) lvl = 3;
    else lvl = 4;
    const int offs[5] = {0, 65536, 81920, 86016, 87040};
    const int lp   = pix - offs[lvl];
    const int lw2  = 8 - lvl;
    const int row  = lp >> lw2;
    const int col  = lp & ((1 << lw2) - 1);
    const int strd = 4 << lvl;

    float acc[18];
#pragma unroll
    for (int j = 0; j < 12; j++) acc[j] = BL[j];
#pragma unroll
    for (int j = 0; j < 6; j++)  acc[12 + j] = BS[j];

    const float* hp = g_h + pix;
#pragma unroll 4
    for (int ic = 0; ic < 256; ic++) {
        float v = hp[(size_t)ic * HTOT];
#pragma unroll
        for (int j = 0; j < 12; j++) acc[j] = fmaf(WL[j][ic], v, acc[j]);
#pragma unroll
        for (int j = 0; j < 6; j++)  acc[12 + j] = fmaf(WS[j][ic], v, acc[12 + j]);
    }

    const float y  = (float)(row * strd);
    const float xx = (float)(col * strd);
    const float sr[3] = {0.70710678118654752f, 1.0f, 1.41421356237309505f};
#pragma unroll
    for (int a = 0; a < 3; a++) {
        float hs = (float)(strd * 8) * sr[a];
        float ws = (float)(strd * 8) * sr[2 - a];
        float a0 = __fadd_rn(y,  -0.5f * hs);
        float a1 = __fadd_rn(xx, -0.5f * ws);
        float a2 = __fadd_rn(y,   0.5f * hs);
        float a3 = __fadd_rn(xx,  0.5f * ws);
        float ah = __fadd_rn(a2, -a0);
        float aw = __fadd_rn(a3, -a1);
        float acy = __fadd_rn(a0, __fmul_rn(0.5f, ah));
        float acx = __fadd_rn(a1, __fmul_rn(0.5f, aw));
        float dy = acc[a * 4 + 0], dx = acc[a * 4 + 1];
        float dh = acc[a * 4 + 2], dw = acc[a * 4 + 3];
        float cy = __fadd_rn(__fmul_rn(dy, ah), acy);
        float cx = __fadd_rn(__fmul_rn(dx, aw), acx);
        float bh = __fmul_rn(expf(dh), ah);
        float bw = __fmul_rn(expf(dw), aw);
        float b0 = fminf(fmaxf(__fadd_rn(cy, -__fmul_rn(0.5f, bh)), 0.f), 1024.f);
        float b1 = fminf(fmaxf(__fadd_rn(cx, -__fmul_rn(0.5f, bw)), 0.f), 1024.f);
        float b2 = fminf(fmaxf(__fadd_rn(cy,  __fmul_rn(0.5f, bh)), 0.f), 1024.f);
        float b3 = fminf(fmaxf(__fadd_rn(cx,  __fmul_rn(0.5f, bw)), 0.f), 1024.f);

        float s0 = acc[12 + a * 2], s1 = acc[12 + a * 2 + 1];
        float m  = fmaxf(s0, s1);
        float e0 = expf(__fadd_rn(s0, -m));
        float e1 = expf(__fadd_rn(s1, -m));
        float fg = __fdiv_rn(e1, __fadd_rn(e0, e1));

        float hh  = __fadd_rn(b2, -b0);
        float ww2 = __fadd_rn(b3, -b1);
        float scv = (hh >= 16.f && ww2 >= 16.f) ? fg : NEGV;

        int aid = pix * 3 + a;
        g_boxes[aid]  = make_float4(b0, b1, b2, b3);
        g_scores[aid] = scv;
    }
}

// ---------------- exact top-6000 via 4-pass radix select ----------------
__device__ __forceinline__ unsigned int fkey(float f) {
    unsigned int u = __float_as_uint(f);
    return u ^ ((u & 0x80000000u) ? 0xFFFFFFFFu : 0x80000000u);
}

__global__ void topk_init() {
    int t = threadIdx.x;
    if (t < 256) g_hist[t] = 0;
    if (t == 0) { g_prefix = 0; g_above = 0; g_remain = PRE_NMS_N; g_ctr = 0; g_tiectr = 0; }
}

__global__ void topk_hist(int shift, unsigned int mask) {
    __shared__ unsigned int sh[256];
    if (threadIdx.x < 256) sh[threadIdx.x] = 0;
    __syncthreads();
    unsigned int pref = g_prefix;
    for (int i = blockIdx.x * blockDim.x + threadIdx.x; i < NANCH; i += gridDim.x * blockDim.x) {
        unsigned int k = fkey(g_scores[i]);
        if ((k & mask) == (pref & mask)) atomicAdd(&sh[(k >> shift) & 255u], 1u);
    }
    __syncthreads();
    if (threadIdx.x < 256 && sh[threadIdx.x]) atomicAdd(&g_hist[threadIdx.x], sh[threadIdx.x]);
}

__global__ void topk_select(int shift) {
    __shared__ unsigned int h[256];
    int t = threadIdx.x;
    h[t] = g_hist[t];
    __syncthreads();
    if (t == 0) {
        unsigned int remain = g_remain;
        unsigned int cum = 0;
        int b = 255;
        for (; b > 0; b--) {
            if (cum + h[b] >= remain) break;
            cum += h[b];
        }
        g_above  = g_above + cum;
        g_remain = remain - cum;
        g_prefix = g_prefix | ((unsigned int)b << shift);
    }
    __syncthreads();
    g_hist[t] = 0;
}

__global__ void topk_compact() {
    unsigned int kt = g_prefix;
    for (int i = blockIdx.x * blockDim.x + threadIdx.x; i < NANCH; i += gridDim.x * blockDim.x) {
        float s = g_scores[i];
        unsigned int k = fkey(s);
        if (k > kt) {
            int p = atomicAdd(&g_ctr, 1);
            g_tb[p] = g_boxes[i];
            g_ts[p] = s;
            g_ti[p] = i;
        } else if (k == kt) {
            int p = atomicAdd(&g_tiectr, 1);
            if (p < TIE_CAP) g_ties[p] = i;
        }
    }
}

__global__ void topk_ties() {
    int need = (int)g_remain;
    int base = (int)g_above;
    int M = g_tiectr;
    if (M > TIE_CAP) M = TIE_CAP;
    for (int i = threadIdx.x; i < M; i += blockDim.x) {
        int idx = g_ties[i];
        int rank = 0;
        for (int j = 0; j < M; j++) rank += (g_ties[j] < idx) ? 1 : 0;
        if (rank < need) {
            int p = base + rank;
            g_tb[p] = g_boxes[idx];
            g_ts[p] = g_scores[idx];
            g_ti[p] = idx;
        }
    }
}

// ---------------- sequential NMS: register-resident, packed u64 keys ----------
// key = fkey(score)<<32 | ~origidx  -> u64 max == (score desc, origidx asc),
// exactly lax.top_k + argmax tie semantics. Suppression overwrites the score
// half with fkey(NEG), preserving idx bits for deterministic ties.
__global__ __launch_bounds__(1024) void nms_kernel(float* __restrict__ out) {
    __shared__ u64 rk[32];
    __shared__ int rp[32];
    __shared__ float4 curbox;
    __shared__ float cura;
    __shared__ int curpos, curvalid;

    const int t = threadIdx.x;
    float4 bx[6];
    float  ar[6];
    u64    key[6];

#pragma unroll
    for (int k = 0; k < 6; k++) {
        int i = k * 1024 + t;
        if (i < PRE_NMS_N) {
            float4 b = g_tb[i];
            bx[k] = b;
            ar[k] = __fmul_rn(__fadd_rn(b.z, -b.x), __fadd_rn(b.w, -b.y));
            key[k] = ((u64)fkey(g_ts[i]) << 32) | (u64)(unsigned)(~(unsigned)g_ti[i]);
        } else {
            bx[k] = make_float4(0.f, 0.f, 0.f, 0.f);
            ar[k] = 0.f;
            key[k] = 0ull;
        }
    }
    const unsigned vthr = fkey(NEGV * 0.5f);
    const u64 deadhi = ((u64)fkey(NEGV)) << 32;
    __syncthreads();

    for (int it = 0; it < POST_NMS_N; it++) {
        u64 bk = key[0];
        int bp = t;
#pragma unroll
        for (int k = 1; k < 6; k++) {
            if (key[k] > bk) { bk = key[k]; bp = k * 1024 + t; }
        }
#pragma unroll
        for (int d = 16; d > 0; d >>= 1) {
            u64 ok = __shfl_down_sync(0xffffffffu, bk, d);
            int op = __shfl_down_sync(0xffffffffu, bp, d);
            if (ok > bk) { bk = ok; bp = op; }
        }
        if ((t & 31) == 0) { rk[t >> 5] = bk; rp[t >> 5] = bp; }
        __syncthreads();
        if (t < 32) {
            bk = rk[t]; bp = rp[t];
#pragma unroll
            for (int d = 16; d > 0; d >>= 1) {
                u64 ok = __shfl_down_sync(0xffffffffu, bk, d);
                int op = __shfl_down_sync(0xffffffffu, bp, d);
                if (ok > bk) { bk = ok; bp = op; }
            }
            if (t == 0) {
                curpos = bp;
                int valid = ((unsigned)(bk >> 32) > vthr) ? 1 : 0;
                curvalid = valid;
                if (!valid) {
                    out[it * 4 + 0] = 0.f;
                    out[it * 4 + 1] = 0.f;
                    out[it * 4 + 2] = 0.f;
                    out[it * 4 + 3] = 0.f;
                }
            }
        }
        __syncthreads();
        if (curvalid && t == (curpos & 1023)) {
            int k = curpos >> 10;
            float4 b = bx[k];
            curbox = b;
            cura = ar[k];
            out[it * 4 + 0] = b.x;
            out[it * 4 + 1] = b.y;
            out[it * 4 + 2] = b.z;
            out[it * 4 + 3] = b.w;
            key[k] = deadhi | (key[k] & 0xFFFFFFFFull);
        }
        __syncthreads();
        if (curvalid) {
            float4 bb = curbox;
            float a1 = cura;
#pragma unroll
            for (int k = 0; k < 6; k++) {
                float4 c = bx[k];
                float ty = fmaxf(bb.x, c.x);
                float tx = fmaxf(bb.y, c.y);
                float by = fminf(bb.z, c.z);
                float bxx = fminf(bb.w, c.w);
                float inter = __fmul_rn(fmaxf(__fadd_rn(by, -ty), 0.f),
                                        fmaxf(__fadd_rn(bxx, -tx), 0.f));
                if (inter > 0.f) {
                    float iou = __fdiv_rn(inter,
                        fmaxf(__fadd_rn(__fadd_rn(a1, ar[k]), -inter), 1e-9f));
                    if (iou > 0.7f) key[k] = deadhi | (key[k] & 0xFFFFFFFFull);
                }
            }
        }
        // no trailing sync needed: next iteration's first sync orders everything
    }
}

// ---------------- host launcher ----------------
extern "C" void kernel_launch(void* const* d_in, const int* in_sizes, int n_in,
                              void* d_out, int out_size)
{
    (void)in_sizes; (void)n_in; (void)out_size;
    const float* p2 = (const float*)d_in[0];
    const float* p3 = (const float*)d_in[1];
    const float* p4 = (const float*)d_in[2];
    const float* p5 = (const float*)d_in[3];
    const float* p6 = (const float*)d_in[4];
    const float* conv_w  = (const float*)d_in[5];
    const float* conv_b  = (const float*)d_in[6];
    const float* loc_w   = (const float*)d_in[7];
    const float* loc_b   = (const float*)d_in[8];
    const float* score_w = (const float*)d_in[9];
    const float* score_b = (const float*)d_in[10];
    float* out = (float*)d_out;

    cudaFuncSetAttribute(conv_all, cudaFuncAttributeMaxDynamicSharedMemorySize, CONV_SMEM);

    // 5 dummy launches so ncu (-s 5 -c 1) captures conv_all
    for (int i = 0; i < 5; i++) dummy_k<<<1, 32>>>();

    conv_all<<<1364, 256, CONV_SMEM>>>(p2, p3, p4, p5, p6, conv_w, conv_b);

    heads_decode<<<682, 128>>>(loc_w, loc_b, score_w, score_b);

    topk_init<<<1, 256>>>();
    const int shifts[4] = {24, 16, 8, 0};
    const unsigned int masks[4] = {0x00000000u, 0xFF000000u, 0xFFFF0000u, 0xFFFFFF00u};
    for (int p = 0; p < 4; p++) {
        topk_hist<<<512, 256>>>(shifts[p], masks[p]);
        topk_select<<<1, 256>>>(shifts[p]);
    }
    topk_compact<<<512, 256>>>();
    topk_ties<<<1, 1024>>>();

    nms_kernel<<<1, 1024>>>(out);
}

// round 5
// speedup vs baseline: 1.8353x; 1.2045x over previous
#include <cuda_runtime.h>
#include <math.h>

#define HTOT 87296
#define NANCH 261888
#define PRE_NMS_N 6000
#define POST_NMS_N 300
#define NEGV -1000000000.0f
#define TIE_CAP 16384
#define STTOT 21824

typedef unsigned long long u64;

// ---------------- device scratch ----------------
static __device__ __align__(16) float g_h[(size_t)256 * HTOT];
static __device__ __align__(16) float g_V[(size_t)16 * 256 * STTOT];  // 357MB winograd input
static __device__ __align__(16) float g_U[(size_t)16 * 256 * 512];    // 8MB transformed weights (oc-dup)
static __device__ float4 g_boxes[NANCH];
static __device__ float  g_scores[NANCH];
static __device__ float4 g_tb[PRE_NMS_N];
static __device__ float  g_ts[PRE_NMS_N];
static __device__ int    g_ti[PRE_NMS_N];
static __device__ unsigned int g_hist[256];
static __device__ unsigned int g_prefix, g_above, g_remain;
static __device__ int g_ctr, g_tiectr;
static __device__ int g_ties[TIE_CAP];

__constant__ float c_AT0[4] = {1.f, 1.f, 1.f, 0.f};
__constant__ float c_AT1[4] = {0.f, 1.f, -1.f, -1.f};

// ---------------- f32x2 helpers ----------------
__device__ __forceinline__ void ffma2(u64& d, u64 a, u64 b) {
    asm("fma.rn.f32x2 %0, %1, %2, %0;" : "+l"(d) : "l"(a), "l"(b));
}
__device__ __forceinline__ void unpk(float& lo, float& hi, u64 v) {
    asm("mov.b64 {%0,%1}, %2;" : "=f"(lo), "=f"(hi) : "l"(v));
}
__device__ __forceinline__ u64 dup2(float v) {
    u64 r;
    asm("mov.b64 %0, {%1, %2};" : "=l"(r) : "f"(v), "f"(v));
    return r;
}

__global__ void dummy_k() {}

// ---------------- W0: weight transform U = G w G^T ----------------
__global__ __launch_bounds__(256) void w0_wtrans(const float* __restrict__ w) {
    int oc = blockIdx.x;
    int ic = threadIdx.x;
    const float* g = w + ((size_t)oc * 256 + ic) * 9;
    float g0 = g[0], g1 = g[1], g2 = g[2];
    float g3 = g[3], g4 = g[4], g5 = g[5];
    float g6 = g[6], g7 = g[7], g8 = g[8];

    float T[4][3];
    T[0][0] = g0; T[0][1] = g1; T[0][2] = g2;
    T[1][0] = 0.5f * (g0 + g3 + g6); T[1][1] = 0.5f * (g1 + g4 + g7); T[1][2] = 0.5f * (g2 + g5 + g8);
    T[2][0] = 0.5f * (g0 - g3 + g6); T[2][1] = 0.5f * (g1 - g4 + g7); T[2][2] = 0.5f * (g2 - g5 + g8);
    T[3][0] = g6; T[3][1] = g7; T[3][2] = g8;

#pragma unroll
    for (int r = 0; r < 4; r++) {
        float u0 = T[r][0];
        float u1 = 0.5f * (T[r][0] + T[r][1] + T[r][2]);
        float u2 = 0.5f * (T[r][0] - T[r][1] + T[r][2]);
        float u3 = T[r][2];
        float uv[4] = {u0, u1, u2, u3};
#pragma unroll
        for (int c = 0; c < 4; c++) {
            int k = r * 4 + c;
            size_t base = ((size_t)k * 256 + ic) * 512 + oc * 2;
            g_U[base] = uv[c];
            g_U[base + 1] = uv[c];
        }
    }
}

// ---------------- W1: input transform V = B^T d B ----------------
__global__ __launch_bounds__(256) void w1_xtrans(
    const float* __restrict__ p2, const float* __restrict__ p3,
    const float* __restrict__ p4, const float* __restrict__ p5,
    const float* __restrict__ p6)
{
    int stb = blockIdx.x;          // 0..340
    int icg = blockIdx.y;          // 0..63
    int t = threadIdx.x;
    int stl = t & 63;
    int icl = t >> 6;
    int st0 = stb * 64;

    const float* x; int W, lsw, stoff;
    if (st0 < 16384)       { x = p2; W = 256; lsw = 7; stoff = 0; }
    else if (st0 < 20480)  { x = p3; W = 128; lsw = 6; stoff = 16384; }
    else if (st0 < 21504)  { x = p4; W = 64;  lsw = 5; stoff = 20480; }
    else if (st0 < 21760)  { x = p5; W = 32;  lsw = 4; stoff = 21504; }
    else                   { x = p6; W = 16;  lsw = 3; stoff = 21760; }
    int SW = W >> 1;

    int ic = icg * 4 + icl;
    int st = st0 + stl;
    int sidx = st - stoff;
    int sy = sidx >> lsw;
    int sx = sidx & (SW - 1);
    int py = 2 * sy - 1;
    int px = 2 * sx - 1;
    const float* xp = x + (size_t)ic * W * W;

    float d[4][4];
#pragma unroll
    for (int r = 0; r < 4; r++) {
        int yy = py + r;
        bool yok = (yy >= 0) && (yy < W);
#pragma unroll
        for (int c = 0; c < 4; c++) {
            int xx = px + c;
            d[r][c] = (yok && xx >= 0 && xx < W) ? xp[yy * W + xx] : 0.f;
        }
    }
    // rows: B^T applied along y
    float e[4][4];
#pragma unroll
    for (int c = 0; c < 4; c++) {
        e[0][c] = d[0][c] - d[2][c];
        e[1][c] = d[1][c] + d[2][c];
        e[2][c] = d[2][c] - d[1][c];
        e[3][c] = d[1][c] - d[3][c];
    }
    float V[4][4];
#pragma unroll
    for (int r = 0; r < 4; r++) {
        V[r][0] = e[r][0] - e[r][2];
        V[r][1] = e[r][1] + e[r][2];
        V[r][2] = e[r][2] - e[r][1];
        V[r][3] = e[r][1] - e[r][3];
    }
    size_t base = (size_t)ic * STTOT + st;
#pragma unroll
    for (int r = 0; r < 4; r++)
#pragma unroll
        for (int c = 0; c < 4; c++)
            g_V[(size_t)(r * 4 + c) * 256 * STTOT + base] = V[r][c];
}

// ---------------- W2: 16 fused GEMMs + output transform + bias/relu -------
// block = 64 oc x 64 supertiles; thread = 4 oc x 4 st (2 st-pairs).
__global__ __launch_bounds__(256, 2) void w2_gemm(const float* __restrict__ bias) {
    __shared__ __align__(16) float Vs[16][64];
    __shared__ __align__(16) float Us[16][128];

    int t = threadIdx.x;
    int stb = blockIdx.x;          // 0..340
    int ocb = blockIdx.y;          // 0..3
    int ts = t & 15;
    int to = t >> 4;
    int st0 = stb * 64;

    int W, lsw, stoff, pixoff;
    if (st0 < 16384)       { W = 256; lsw = 7; stoff = 0;     pixoff = 0; }
    else if (st0 < 20480)  { W = 128; lsw = 6; stoff = 16384; pixoff = 65536; }
    else if (st0 < 21504)  { W = 64;  lsw = 5; stoff = 20480; pixoff = 81920; }
    else if (st0 < 21760)  { W = 32;  lsw = 4; stoff = 21504; pixoff = 86016; }
    else                   { W = 16;  lsw = 3; stoff = 21760; pixoff = 87040; }
    int SW = W >> 1;

    u64 out[4][2][4];   // [oc][st-pair][out pos oy*2+ox]
#pragma unroll
    for (int o = 0; o < 4; o++)
#pragma unroll
        for (int p = 0; p < 2; p++)
#pragma unroll
            for (int q = 0; q < 4; q++) out[o][p][q] = 0ull;

    const int vic = t >> 4, vj = (t & 15) * 4;
    const int uj = (t & 15) * 8;

    for (int k = 0; k < 16; k++) {
        u64 m[4][2];
#pragma unroll
        for (int o = 0; o < 4; o++) { m[o][0] = 0ull; m[o][1] = 0ull; }

        for (int ic0 = 0; ic0 < 256; ic0 += 16) {
            __syncthreads();
            {
                const float* src = g_V + ((size_t)k * 256 + ic0 + vic) * STTOT + st0 + vj;
                *(float4*)&Vs[vic][vj] = *(const float4*)src;
                const float* usrc = g_U + ((size_t)k * 256 + ic0 + vic) * 512 + ocb * 128 + uj;
                *(float4*)&Us[vic][uj]     = *(const float4*)usrc;
                *(float4*)&Us[vic][uj + 4] = *(const float4*)(usrc + 4);
            }
            __syncthreads();
#pragma unroll
            for (int ic = 0; ic < 16; ic++) {
                const u64* vp = (const u64*)&Vs[ic][ts * 4];
                u64 v0 = vp[0], v1 = vp[1];
                const u64* up = (const u64*)&Us[ic][to * 8];
                u64 u0 = up[0], u1 = up[1], u2 = up[2], u3 = up[3];
                ffma2(m[0][0], v0, u0); ffma2(m[0][1], v1, u0);
                ffma2(m[1][0], v0, u1); ffma2(m[1][1], v1, u1);
                ffma2(m[2][0], v0, u2); ffma2(m[2][1], v1, u2);
                ffma2(m[3][0], v0, u3); ffma2(m[3][1], v1, u3);
            }
        }
        // fold M_k into output accumulators (A^T M A), coeffs in {-1,0,1}
        int ky = k >> 2, kx = k & 3;
        float cy0 = c_AT0[ky], cy1 = c_AT1[ky];
        float cx0 = c_AT0[kx], cx1 = c_AT1[kx];
        float cc[4] = {cy0 * cx0, cy0 * cx1, cy1 * cx0, cy1 * cx1};
#pragma unroll
        for (int q = 0; q < 4; q++) {
            u64 cd = dup2(cc[q]);
#pragma unroll
            for (int o = 0; o < 4; o++) {
                ffma2(out[o][0][q], m[o][0], cd);
                ffma2(out[o][1][q], m[o][1], cd);
            }
        }
    }

    // epilogue: bias + relu, float2 stores
#pragma unroll
    for (int o = 0; o < 4; o++) {
        int oc = ocb * 64 + to * 4 + o;
        float bv = bias[oc];
        float* hp = g_h + (size_t)oc * HTOT + pixoff;
#pragma unroll
        for (int p = 0; p < 2; p++) {
            float v00l, v00h, v01l, v01h, v10l, v10h, v11l, v11h;
            unpk(v00l, v00h, out[o][p][0]);   // (oy0,ox0) for st e=0 / e=1
            unpk(v01l, v01h, out[o][p][1]);   // (oy0,ox1)
            unpk(v10l, v10h, out[o][p][2]);   // (oy1,ox0)
            unpk(v11l, v11h, out[o][p][3]);   // (oy1,ox1)
#pragma unroll
            for (int e = 0; e < 2; e++) {
                int sidx = st0 - stoff + ts * 4 + p * 2 + e;
                int sy = sidx >> lsw;
                int sx = sidx & (SW - 1);
                float a00 = e ? v00h : v00l;
                float a01 = e ? v01h : v01l;
                float a10 = e ? v10h : v10l;
                float a11 = e ? v11h : v11l;
                float2 r0, r1;
                r0.x = fmaxf(a00 + bv, 0.f);
                r0.y = fmaxf(a01 + bv, 0.f);
                r1.x = fmaxf(a10 + bv, 0.f);
                r1.y = fmaxf(a11 + bv, 0.f);
                *(float2*)&hp[(2 * sy) * W + 2 * sx]     = r0;
                *(float2*)&hp[(2 * sy + 1) * W + 2 * sx] = r1;
            }
        }
    }
}

// ---------------- heads: 1x1 convs + softmax + decode + min-size ----------------
__global__ __launch_bounds__(128) void heads_decode(
    const float* __restrict__ lw, const float* __restrict__ lb,
    const float* __restrict__ sw, const float* __restrict__ sb)
{
    __shared__ float WL[12][256];
    __shared__ float WS[6][256];
    __shared__ float BL[12], BS[6];
    const int t = threadIdx.x;
    for (int i = t; i < 12 * 256; i += 128) WL[i >> 8][i & 255] = lw[i];
    for (int i = t; i < 6 * 256; i += 128)  WS[i >> 8][i & 255] = sw[i];
    if (t < 12) BL[t] = lb[t];
    if (t < 6)  BS[t] = sb[t];
    __syncthreads();

    const int pix = blockIdx.x * 128 + t;
    int lvl;
    if (pix < 65536) lvl = 0;
    else if (pix < 81920) lvl = 1;
    else if (pix < 86016) lvl = 2;
    else if (pix < 87040) lvl = 3;
    else lvl = 4;
    const int offs[5] = {0, 65536, 81920, 86016, 87040};
    const int lp   = pix - offs[lvl];
    const int lw2  = 8 - lvl;
    const int row  = lp >> lw2;
    const int col  = lp & ((1 << lw2) - 1);
    const int strd = 4 << lvl;

    float acc[18];
#pragma unroll
    for (int j = 0; j < 12; j++) acc[j] = BL[j];
#pragma unroll
    for (int j = 0; j < 6; j++)  acc[12 + j] = BS[j];

    const float* hp = g_h + pix;
#pragma unroll 4
    for (int ic = 0; ic < 256; ic++) {
        float v = hp[(size_t)ic * HTOT];
#pragma unroll
        for (int j = 0; j < 12; j++) acc[j] = fmaf(WL[j][ic], v, acc[j]);
#pragma unroll
        for (int j = 0; j < 6; j++)  acc[12 + j] = fmaf(WS[j][ic], v, acc[12 + j]);
    }

    const float y  = (float)(row * strd);
    const float xx = (float)(col * strd);
    const float sr[3] = {0.70710678118654752f, 1.0f, 1.41421356237309505f};
#pragma unroll
    for (int a = 0; a < 3; a++) {
        float hs = (float)(strd * 8) * sr[a];
        float ws = (float)(strd * 8) * sr[2 - a];
        float a0 = __fadd_rn(y,  -0.5f * hs);
        float a1 = __fadd_rn(xx, -0.5f * ws);
        float a2 = __fadd_rn(y,   0.5f * hs);
        float a3 = __fadd_rn(xx,  0.5f * ws);
        float ah = __fadd_rn(a2, -a0);
        float aw = __fadd_rn(a3, -a1);
        float acy = __fadd_rn(a0, __fmul_rn(0.5f, ah));
        float acx = __fadd_rn(a1, __fmul_rn(0.5f, aw));
        float dy = acc[a * 4 + 0], dx = acc[a * 4 + 1];
        float dh = acc[a * 4 + 2], dw = acc[a * 4 + 3];
        float cy = __fadd_rn(__fmul_rn(dy, ah), acy);
        float cx = __fadd_rn(__fmul_rn(dx, aw), acx);
        float bh = __fmul_rn(expf(dh), ah);
        float bw = __fmul_rn(expf(dw), aw);
        float b0 = fminf(fmaxf(__fadd_rn(cy, -__fmul_rn(0.5f, bh)), 0.f), 1024.f);
        float b1 = fminf(fmaxf(__fadd_rn(cx, -__fmul_rn(0.5f, bw)), 0.f), 1024.f);
        float b2 = fminf(fmaxf(__fadd_rn(cy,  __fmul_rn(0.5f, bh)), 0.f), 1024.f);
        float b3 = fminf(fmaxf(__fadd_rn(cx,  __fmul_rn(0.5f, bw)), 0.f), 1024.f);

        float s0 = acc[12 + a * 2], s1 = acc[12 + a * 2 + 1];
        float m  = fmaxf(s0, s1);
        float e0 = expf(__fadd_rn(s0, -m));
        float e1 = expf(__fadd_rn(s1, -m));
        float fg = __fdiv_rn(e1, __fadd_rn(e0, e1));

        float hh  = __fadd_rn(b2, -b0);
        float ww2 = __fadd_rn(b3, -b1);
        float scv = (hh >= 16.f && ww2 >= 16.f) ? fg : NEGV;

        int aid = pix * 3 + a;
        g_boxes[aid]  = make_float4(b0, b1, b2, b3);
        g_scores[aid] = scv;
    }
}

// ---------------- exact top-6000 via 4-pass radix select ----------------
__device__ __forceinline__ unsigned int fkey(float f) {
    unsigned int u = __float_as_uint(f);
    return u ^ ((u & 0x80000000u) ? 0xFFFFFFFFu : 0x80000000u);
}

__global__ void topk_init() {
    int t = threadIdx.x;
    if (t < 256) g_hist[t] = 0;
    if (t == 0) { g_prefix = 0; g_above = 0; g_remain = PRE_NMS_N; g_ctr = 0; g_tiectr = 0; }
}

__global__ void topk_hist(int shift, unsigned int mask) {
    __shared__ unsigned int sh[256];
    if (threadIdx.x < 256) sh[threadIdx.x] = 0;
    __syncthreads();
    unsigned int pref = g_prefix;
    for (int i = blockIdx.x * blockDim.x + threadIdx.x; i < NANCH; i += gridDim.x * blockDim.x) {
        unsigned int k = fkey(g_scores[i]);
        if ((k & mask) == (pref & mask)) atomicAdd(&sh[(k >> shift) & 255u], 1u);
    }
    __syncthreads();
    if (threadIdx.x < 256 && sh[threadIdx.x]) atomicAdd(&g_hist[threadIdx.x], sh[threadIdx.x]);
}

__global__ void topk_select(int shift) {
    __shared__ unsigned int h[256];
    int t = threadIdx.x;
    h[t] = g_hist[t];
    __syncthreads();
    if (t == 0) {
        unsigned int remain = g_remain;
        unsigned int cum = 0;
        int b = 255;
        for (; b > 0; b--) {
            if (cum + h[b] >= remain) break;
            cum += h[b];
        }
        g_above  = g_above + cum;
        g_remain = remain - cum;
        g_prefix = g_prefix | ((unsigned int)b << shift);
    }
    __syncthreads();
    g_hist[t] = 0;
}

__global__ void topk_compact() {
    unsigned int kt = g_prefix;
    for (int i = blockIdx.x * blockDim.x + threadIdx.x; i < NANCH; i += gridDim.x * blockDim.x) {
        float s = g_scores[i];
        unsigned int k = fkey(s);
        if (k > kt) {
            int p = atomicAdd(&g_ctr, 1);
            g_tb[p] = g_boxes[i];
            g_ts[p] = s;
            g_ti[p] = i;
        } else if (k == kt) {
            int p = atomicAdd(&g_tiectr, 1);
            if (p < TIE_CAP) g_ties[p] = i;
        }
    }
}

__global__ void topk_ties() {
    int need = (int)g_remain;
    int base = (int)g_above;
    int M = g_tiectr;
    if (M > TIE_CAP) M = TIE_CAP;
    for (int i = threadIdx.x; i < M; i += blockDim.x) {
        int idx = g_ties[i];
        int rank = 0;
        for (int j = 0; j < M; j++) rank += (g_ties[j] < idx) ? 1 : 0;
        if (rank < need) {
            int p = base + rank;
            g_tb[p] = g_boxes[idx];
            g_ts[p] = g_scores[idx];
            g_ti[p] = idx;
        }
    }
}

// ---------------- sequential NMS: register-resident, packed u64 keys ----------
__global__ __launch_bounds__(1024) void nms_kernel(float* __restrict__ out) {
    __shared__ u64 rk[32];
    __shared__ int rp[32];
    __shared__ float4 curbox;
    __shared__ float cura;
    __shared__ int curpos, curvalid;

    const int t = threadIdx.x;
    float4 bx[6];
    float  ar[6];
    u64    key[6];

#pragma unroll
    for (int k = 0; k < 6; k++) {
        int i = k * 1024 + t;
        if (i < PRE_NMS_N) {
            float4 b = g_tb[i];
            bx[k] = b;
            ar[k] = __fmul_rn(__fadd_rn(b.z, -b.x), __fadd_rn(b.w, -b.y));
            key[k] = ((u64)fkey(g_ts[i]) << 32) | (u64)(unsigned)(~(unsigned)g_ti[i]);
        } else {
            bx[k] = make_float4(0.f, 0.f, 0.f, 0.f);
            ar[k] = 0.f;
            key[k] = 0ull;
        }
    }
    const unsigned vthr = fkey(NEGV * 0.5f);
    const u64 deadhi = ((u64)fkey(NEGV)) << 32;
    __syncthreads();

    for (int it = 0; it < POST_NMS_N; it++) {
        u64 bk = key[0];
        int bp = t;
#pragma unroll
        for (int k = 1; k < 6; k++) {
            if (key[k] > bk) { bk = key[k]; bp = k * 1024 + t; }
        }
#pragma unroll
        for (int d = 16; d > 0; d >>= 1) {
            u64 ok = __shfl_down_sync(0xffffffffu, bk, d);
            int op = __shfl_down_sync(0xffffffffu, bp, d);
            if (ok > bk) { bk = ok; bp = op; }
        }
        if ((t & 31) == 0) { rk[t >> 5] = bk; rp[t >> 5] = bp; }
        __syncthreads();
        if (t < 32) {
            bk = rk[t]; bp = rp[t];
#pragma unroll
            for (int d = 16; d > 0; d >>= 1) {
                u64 ok = __shfl_down_sync(0xffffffffu, bk, d);
                int op = __shfl_down_sync(0xffffffffu, bp, d);
                if (ok > bk) { bk = ok; bp = op; }
            }
            if (t == 0) {
                curpos = bp;
                int valid = ((unsigned)(bk >> 32) > vthr) ? 1 : 0;
                curvalid = valid;
                if (!valid) {
                    out[it * 4 + 0] = 0.f;
                    out[it * 4 + 1] = 0.f;
                    out[it * 4 + 2] = 0.f;
                    out[it * 4 + 3] = 0.f;
                }
            }
        }
        __syncthreads();
        if (curvalid && t == (curpos & 1023)) {
            int k = curpos >> 10;
            float4 b = bx[k];
            curbox = b;
            cura = ar[k];
            out[it * 4 + 0] = b.x;
            out[it * 4 + 1] = b.y;
            out[it * 4 + 2] = b.z;
            out[it * 4 + 3] = b.w;
            key[k] = deadhi | (key[k] & 0xFFFFFFFFull);
        }
        __syncthreads();
        if (curvalid) {
            float4 bb = curbox;
            float a1 = cura;
#pragma unroll
            for (int k = 0; k < 6; k++) {
                float4 c = bx[k];
                float ty = fmaxf(bb.x, c.x);
                float tx = fmaxf(bb.y, c.y);
                float by = fminf(bb.z, c.z);
                float bxx = fminf(bb.w, c.w);
                float inter = __fmul_rn(fmaxf(__fadd_rn(by, -ty), 0.f),
                                        fmaxf(__fadd_rn(bxx, -tx), 0.f));
                if (inter > 0.f) {
                    float iou = __fdiv_rn(inter,
                        fmaxf(__fadd_rn(__fadd_rn(a1, ar[k]), -inter), 1e-9f));
                    if (iou > 0.7f) key[k] = deadhi | (key[k] & 0xFFFFFFFFull);
                }
            }
        }
    }
}

// ---------------- host launcher ----------------
extern "C" void kernel_launch(void* const* d_in, const int* in_sizes, int n_in,
                              void* d_out, int out_size)
{
    (void)in_sizes; (void)n_in; (void)out_size;
    const float* p2 = (const float*)d_in[0];
    const float* p3 = (const float*)d_in[1];
    const float* p4 = (const float*)d_in[2];
    const float* p5 = (const float*)d_in[3];
    const float* p6 = (const float*)d_in[4];
    const float* conv_w  = (const float*)d_in[5];
    const float* conv_b  = (const float*)d_in[6];
    const float* loc_w   = (const float*)d_in[7];
    const float* loc_b   = (const float*)d_in[8];
    const float* score_w = (const float*)d_in[9];
    const float* score_b = (const float*)d_in[10];
    float* out = (float*)d_out;

    // 3 dummies: w2_gemm lands at 0-based launch index 5 for ncu -s 5 -c 1
    for (int i = 0; i < 3; i++) dummy_k<<<1, 32>>>();

    w0_wtrans<<<256, 256>>>(conv_w);
    w1_xtrans<<<dim3(341, 64), 256>>>(p2, p3, p4, p5, p6);
    w2_gemm<<<dim3(341, 4), 256>>>(conv_b);

    heads_decode<<<682, 128>>>(loc_w, loc_b, score_w, score_b);

    topk_init<<<1, 256>>>();
    const int shifts[4] = {24, 16, 8, 0};
    const unsigned int masks[4] = {0x00000000u, 0xFF000000u, 0xFFFF0000u, 0xFFFFFF00u};
    for (int p = 0; p < 4; p++) {
        topk_hist<<<512, 256>>>(shifts[p], masks[p]);
        topk_select<<<1, 256>>>(shifts[p]);
    }
    topk_compact<<<512, 256>>>();
    topk_ties<<<1, 1024>>>();

    nms_kernel<<<1, 1024>>>(out);
}

// round 7
// speedup vs baseline: 2.4776x; 1.3500x over previous
#include <cuda_runtime.h>
#include <math.h>

#define HTOT 87296
#define NANCH 261888
#define PRE_NMS_N 6000
#define POST_NMS_N 300
#define NEGV -1000000000.0f
#define TIE_CAP 16384
#define STTOT 21824

typedef unsigned long long u64;

// ---------------- device scratch ----------------
static __device__ __align__(16) float g_h[(size_t)256 * HTOT];
static __device__ __align__(16) float g_V[(size_t)16 * 256 * STTOT];  // winograd V; reused in-place as M
static __device__ __align__(16) float g_U[(size_t)16 * 256 * 512];    // transformed weights (oc-dup)
#define g_M g_V   // safe alias: w2 block (stb,k) reads V[k][:,st-tile] fully before writing M[k][:,st-tile]
static __device__ float4 g_boxes[NANCH];
static __device__ float  g_scores[NANCH];
static __device__ float4 g_tb[PRE_NMS_N];
static __device__ float  g_ts[PRE_NMS_N];
static __device__ int    g_ti[PRE_NMS_N];
static __device__ unsigned int g_hist[256];
static __device__ unsigned int g_prefix, g_above, g_remain;
static __device__ int g_ctr, g_tiectr;
static __device__ int g_ties[TIE_CAP];

// ---------------- f32x2 helpers ----------------
__device__ __forceinline__ void ffma2(u64& d, u64 a, u64 b) {
    asm("fma.rn.f32x2 %0, %1, %2, %0;" : "+l"(d) : "l"(a), "l"(b));
}

__global__ void dummy_k() {}

// ---------------- W0: weight transform U = G w G^T ----------------
__global__ __launch_bounds__(256) void w0_wtrans(const float* __restrict__ w) {
    int oc = blockIdx.x;
    int ic = threadIdx.x;
    const float* g = w + ((size_t)oc * 256 + ic) * 9;
    float g0 = g[0], g1 = g[1], g2 = g[2];
    float g3 = g[3], g4 = g[4], g5 = g[5];
    float g6 = g[6], g7 = g[7], g8 = g[8];

    float T[4][3];
    T[0][0] = g0; T[0][1] = g1; T[0][2] = g2;
    T[1][0] = 0.5f * (g0 + g3 + g6); T[1][1] = 0.5f * (g1 + g4 + g7); T[1][2] = 0.5f * (g2 + g5 + g8);
    T[2][0] = 0.5f * (g0 - g3 + g6); T[2][1] = 0.5f * (g1 - g4 + g7); T[2][2] = 0.5f * (g2 - g5 + g8);
    T[3][0] = g6; T[3][1] = g7; T[3][2] = g8;

#pragma unroll
    for (int r = 0; r < 4; r++) {
        float u0 = T[r][0];
        float u1 = 0.5f * (T[r][0] + T[r][1] + T[r][2]);
        float u2 = 0.5f * (T[r][0] - T[r][1] + T[r][2]);
        float u3 = T[r][2];
        float uv[4] = {u0, u1, u2, u3};
#pragma unroll
        for (int c = 0; c < 4; c++) {
            int k = r * 4 + c;
            size_t base = ((size_t)k * 256 + ic) * 512 + oc * 2;
            g_U[base] = uv[c];
            g_U[base + 1] = uv[c];
        }
    }
}

// ---------------- W1: input transform V = B^T d B ----------------
__global__ __launch_bounds__(256) void w1_xtrans(
    const float* __restrict__ p2, const float* __restrict__ p3,
    const float* __restrict__ p4, const float* __restrict__ p5,
    const float* __restrict__ p6)
{
    int stb = blockIdx.x;          // 0..340
    int icg = blockIdx.y;          // 0..63
    int t = threadIdx.x;
    int stl = t & 63;
    int icl = t >> 6;
    int st0 = stb * 64;

    const float* x; int W, lsw, stoff;
    if (st0 < 16384)       { x = p2; W = 256; lsw = 7; stoff = 0; }
    else if (st0 < 20480)  { x = p3; W = 128; lsw = 6; stoff = 16384; }
    else if (st0 < 21504)  { x = p4; W = 64;  lsw = 5; stoff = 20480; }
    else if (st0 < 21760)  { x = p5; W = 32;  lsw = 4; stoff = 21504; }
    else                   { x = p6; W = 16;  lsw = 3; stoff = 21760; }
    int SW = W >> 1;

    int ic = icg * 4 + icl;
    int st = st0 + stl;
    int sidx = st - stoff;
    int sy = sidx >> lsw;
    int sx = sidx & (SW - 1);
    int py = 2 * sy - 1;
    int px = 2 * sx - 1;
    const float* xp = x + (size_t)ic * W * W;

    float d[4][4];
#pragma unroll
    for (int r = 0; r < 4; r++) {
        int yy = py + r;
        bool yok = (yy >= 0) && (yy < W);
#pragma unroll
        for (int c = 0; c < 4; c++) {
            int xx = px + c;
            d[r][c] = (yok && xx >= 0 && xx < W) ? xp[yy * W + xx] : 0.f;
        }
    }
    float e[4][4];
#pragma unroll
    for (int c = 0; c < 4; c++) {
        e[0][c] = d[0][c] - d[2][c];
        e[1][c] = d[1][c] + d[2][c];
        e[2][c] = d[2][c] - d[1][c];
        e[3][c] = d[1][c] - d[3][c];
    }
    float V[4][4];
#pragma unroll
    for (int r = 0; r < 4; r++) {
        V[r][0] = e[r][0] - e[r][2];
        V[r][1] = e[r][1] + e[r][2];
        V[r][2] = e[r][2] - e[r][1];
        V[r][3] = e[r][1] - e[r][3];
    }
    size_t base = (size_t)ic * STTOT + st;
#pragma unroll
    for (int r = 0; r < 4; r++)
#pragma unroll
        for (int c = 0; c < 4; c++)
            g_V[(size_t)(r * 4 + c) * 256 * STTOT + base] = V[r][c];
}

// ---------------- W2: pure GEMM per k: M_k = U_k^T V_k (in-place V->M) ----
// block = (stb, k): 256 oc x 64 st x 256 ic. thread = 8 oc x 8 st.
__global__ __launch_bounds__(256, 2) void w2_gemm_k() {
    __shared__ __align__(16) float Vs[8][64];
    __shared__ __align__(16) float Us[8][512];

    const int t   = threadIdx.x;
    const int stb = blockIdx.x;    // 0..340
    const int k   = blockIdx.y;    // 0..15
    const int st0 = stb * 64;
    const int thr_oc = t >> 3;     // 0..31
    const int thr_st = t & 7;      // 0..7

    u64 m[8][4];
#pragma unroll
    for (int o = 0; o < 8; o++)
#pragma unroll
        for (int s = 0; s < 4; s++) m[o][s] = 0ull;

    const float* Vbase = g_V + (size_t)k * 256 * STTOT + st0;
    const float* Ubase = g_U + (size_t)k * 256 * 512;
    const int vr = t >> 5, vc = (t & 31) * 2;

    for (int ic0 = 0; ic0 < 256; ic0 += 8) {
        __syncthreads();
        *(float2*)&Vs[vr][vc] = *(const float2*)(Vbase + (size_t)(ic0 + vr) * STTOT + vc);
        {
            const float4* usrc = (const float4*)(Ubase + (size_t)ic0 * 512);
            float4* udst = (float4*)&Us[0][0];
#pragma unroll
            for (int j = 0; j < 4; j++) udst[j * 256 + t] = usrc[j * 256 + t];
        }
        __syncthreads();
#pragma unroll
        for (int ic = 0; ic < 8; ic++) {
            const ulonglong2* vp = (const ulonglong2*)&Vs[ic][thr_st * 8];
            ulonglong2 va = vp[0], vb = vp[1];
            u64 v[4] = {va.x, va.y, vb.x, vb.y};
            const ulonglong2* up = (const ulonglong2*)&Us[ic][thr_oc * 16];
            ulonglong2 ua = up[0], ub = up[1], uc = up[2], ud = up[3];
            u64 u[8] = {ua.x, ua.y, ub.x, ub.y, uc.x, uc.y, ud.x, ud.y};
#pragma unroll
            for (int o = 0; o < 8; o++)
#pragma unroll
                for (int s = 0; s < 4; s++) ffma2(m[o][s], v[s], u[o]);
        }
    }

    // all V reads for this (k, st-tile) are done; in-place write M over V
    __syncthreads();
#pragma unroll
    for (int o = 0; o < 8; o++) {
        int oc = thr_oc * 8 + o;
        u64* mp = (u64*)(g_M + ((size_t)k * 256 + oc) * STTOT + st0 + thr_st * 8);
        ulonglong2 s0, s1;
        s0.x = m[o][0]; s0.y = m[o][1];
        s1.x = m[o][2]; s1.y = m[o][3];
        *(ulonglong2*)mp = s0;
        *(ulonglong2*)(mp + 2) = s1;
    }
}

// ---------------- W3: output transform A^T M A + bias + relu ----------------
__global__ __launch_bounds__(256) void w3_otrans(const float* __restrict__ bias) {
    const int stb = blockIdx.x;    // 0..340
    const int ocg = blockIdx.y;    // 0..15
    const int t = threadIdx.x;
    const int stl = t & 63;
    const int ocl = t >> 6;
    const int st0 = stb * 64;
    const int st  = st0 + stl;

    int W, lsw, stoff, pixoff;
    if (st0 < 16384)       { W = 256; lsw = 7; stoff = 0;     pixoff = 0; }
    else if (st0 < 20480)  { W = 128; lsw = 6; stoff = 16384; pixoff = 65536; }
    else if (st0 < 21504)  { W = 64;  lsw = 5; stoff = 20480; pixoff = 81920; }
    else if (st0 < 21760)  { W = 32;  lsw = 4; stoff = 21504; pixoff = 86016; }
    else                   { W = 16;  lsw = 3; stoff = 21760; pixoff = 87040; }
    int SW = W >> 1;

    int sidx = st - stoff;
    int sy = sidx >> lsw;
    int sx = sidx & (SW - 1);

#pragma unroll
    for (int o4 = 0; o4 < 4; o4++) {
        int oc = ocg * 16 + ocl * 4 + o4;
        const float* Mp = g_M + (size_t)oc * STTOT + st;
        float Mv[16];
#pragma unroll
        for (int kk = 0; kk < 16; kk++)
            Mv[kk] = Mp[(size_t)kk * 256 * STTOT];

        float e0[4], e1[4];
#pragma unroll
        for (int c = 0; c < 4; c++) {
            e0[c] = Mv[c] + Mv[4 + c] + Mv[8 + c];
            e1[c] = Mv[4 + c] - Mv[8 + c] - Mv[12 + c];
        }
        float o00 = e0[0] + e0[1] + e0[2];
        float o01 = e0[1] - e0[2] - e0[3];
        float o10 = e1[0] + e1[1] + e1[2];
        float o11 = e1[1] - e1[2] - e1[3];

        float bv = bias[oc];
        float* hp = g_h + (size_t)oc * HTOT + pixoff;
        float2 r0, r1;
        r0.x = fmaxf(o00 + bv, 0.f);
        r0.y = fmaxf(o01 + bv, 0.f);
        r1.x = fmaxf(o10 + bv, 0.f);
        r1.y = fmaxf(o11 + bv, 0.f);
        *(float2*)&hp[(2 * sy) * W + 2 * sx]     = r0;
        *(float2*)&hp[(2 * sy + 1) * W + 2 * sx] = r1;
    }
}

// ---------------- heads: 1x1 convs + softmax + decode + min-size ----------------
__global__ __launch_bounds__(128) void heads_decode(
    const float* __restrict__ lw, const float* __restrict__ lb,
    const float* __restrict__ sw, const float* __restrict__ sb)
{
    __shared__ float WL[12][256];
    __shared__ float WS[6][256];
    __shared__ float BL[12], BS[6];
    const int t = threadIdx.x;
    for (int i = t; i < 12 * 256; i += 128) WL[i >> 8][i & 255] = lw[i];
    for (int i = t; i < 6 * 256; i += 128)  WS[i >> 8][i & 255] = sw[i];
    if (t < 12) BL[t] = lb[t];
    if (t < 6)  BS[t] = sb[t];
    __syncthreads();

    const int pix = blockIdx.x * 128 + t;
    int lvl;
    if (pix < 65536) lvl = 0;
    else if (pix < 81920) lvl = 1;
    else if (pix < 86016) lvl = 2;
    else if (pix < 87040) lvl = 3;
    else lvl = 4;
    const int offs[5] = {0, 65536, 81920, 86016, 87040};
    const int lp   = pix - offs[lvl];
    const int lw2  = 8 - lvl;
    const int row  = lp >> lw2;
    const int col  = lp & ((1 << lw2) - 1);
    const int strd = 4 << lvl;

    float acc[18];
#pragma unroll
    for (int j = 0; j < 12; j++) acc[j] = BL[j];
#pragma unroll
    for (int j = 0; j < 6; j++)  acc[12 + j] = BS[j];

    const float* hp = g_h + pix;
#pragma unroll 4
    for (int ic = 0; ic < 256; ic++) {
        float v = hp[(size_t)ic * HTOT];
#pragma unroll
        for (int j = 0; j < 12; j++) acc[j] = fmaf(WL[j][ic], v, acc[j]);
#pragma unroll
        for (int j = 0; j < 6; j++)  acc[12 + j] = fmaf(WS[j][ic], v, acc[12 + j]);
    }

    const float y  = (float)(row * strd);
    const float xx = (float)(col * strd);
    const float sr[3] = {0.70710678118654752f, 1.0f, 1.41421356237309505f};
#pragma unroll
    for (int a = 0; a < 3; a++) {
        float hs = (float)(strd * 8) * sr[a];
        float ws = (float)(strd * 8) * sr[2 - a];
        float a0 = __fadd_rn(y,  -0.5f * hs);
        float a1 = __fadd_rn(xx, -0.5f * ws);
        float a2 = __fadd_rn(y,   0.5f * hs);
        float a3 = __fadd_rn(xx,  0.5f * ws);
        float ah = __fadd_rn(a2, -a0);
        float aw = __fadd_rn(a3, -a1);
        float acy = __fadd_rn(a0, __fmul_rn(0.5f, ah));
        float acx = __fadd_rn(a1, __fmul_rn(0.5f, aw));
        float dy = acc[a * 4 + 0], dx = acc[a * 4 + 1];
        float dh = acc[a * 4 + 2], dw = acc[a * 4 + 3];
        float cy = __fadd_rn(__fmul_rn(dy, ah), acy);
        float cx = __fadd_rn(__fmul_rn(dx, aw), acx);
        float bh = __fmul_rn(expf(dh), ah);
        float bw = __fmul_rn(expf(dw), aw);
        float b0 = fminf(fmaxf(__fadd_rn(cy, -__fmul_rn(0.5f, bh)), 0.f), 1024.f);
        float b1 = fminf(fmaxf(__fadd_rn(cx, -__fmul_rn(0.5f, bw)), 0.f), 1024.f);
        float b2 = fminf(fmaxf(__fadd_rn(cy,  __fmul_rn(0.5f, bh)), 0.f), 1024.f);
        float b3 = fminf(fmaxf(__fadd_rn(cx,  __fmul_rn(0.5f, bw)), 0.f), 1024.f);

        float s0 = acc[12 + a * 2], s1 = acc[12 + a * 2 + 1];
        float m  = fmaxf(s0, s1);
        float e0 = expf(__fadd_rn(s0, -m));
        float e1 = expf(__fadd_rn(s1, -m));
        float fg = __fdiv_rn(e1, __fadd_rn(e0, e1));

        float hh  = __fadd_rn(b2, -b0);
        float ww2 = __fadd_rn(b3, -b1);
        float scv = (hh >= 16.f && ww2 >= 16.f) ? fg : NEGV;

        int aid = pix * 3 + a;
        g_boxes[aid]  = make_float4(b0, b1, b2, b3);
        g_scores[aid] = scv;
    }
}

// ---------------- exact top-6000 via 4-pass radix select ----------------
__device__ __forceinline__ unsigned int fkey(float f) {
    unsigned int u = __float_as_uint(f);
    return u ^ ((u & 0x80000000u) ? 0xFFFFFFFFu : 0x80000000u);
}

__global__ void topk_init() {
    int t = threadIdx.x;
    if (t < 256) g_hist[t] = 0;
    if (t == 0) { g_prefix = 0; g_above = 0; g_remain = PRE_NMS_N; g_ctr = 0; g_tiectr = 0; }
}

__global__ void topk_hist(int shift, unsigned int mask) {
    __shared__ unsigned int sh[256];
    if (threadIdx.x < 256) sh[threadIdx.x] = 0;
    __syncthreads();
    unsigned int pref = g_prefix;
    for (int i = blockIdx.x * blockDim.x + threadIdx.x; i < NANCH; i += gridDim.x * blockDim.x) {
        unsigned int k = fkey(g_scores[i]);
        if ((k & mask) == (pref & mask)) atomicAdd(&sh[(k >> shift) & 255u], 1u);
    }
    __syncthreads();
    if (threadIdx.x < 256 && sh[threadIdx.x]) atomicAdd(&g_hist[threadIdx.x], sh[threadIdx.x]);
}

__global__ void topk_select(int shift) {
    __shared__ unsigned int h[256];
    int t = threadIdx.x;
    h[t] = g_hist[t];
    __syncthreads();
    if (t == 0) {
        unsigned int remain = g_remain;
        unsigned int cum = 0;
        int b = 255;
        for (; b > 0; b--) {
            if (cum + h[b] >= remain) break;
            cum += h[b];
        }
        g_above  = g_above + cum;
        g_remain = remain - cum;
        g_prefix = g_prefix | ((unsigned int)b << shift);
    }
    __syncthreads();
    g_hist[t] = 0;
}

__global__ void topk_compact() {
    unsigned int kt = g_prefix;
    for (int i = blockIdx.x * blockDim.x + threadIdx.x; i < NANCH; i += gridDim.x * blockDim.x) {
        float s = g_scores[i];
        unsigned int k = fkey(s);
        if (k > kt) {
            int p = atomicAdd(&g_ctr, 1);
            g_tb[p] = g_boxes[i];
            g_ts[p] = s;
            g_ti[p] = i;
        } else if (k == kt) {
            int p = atomicAdd(&g_tiectr, 1);
            if (p < TIE_CAP) g_ties[p] = i;
        }
    }
}

__global__ void topk_ties() {
    int need = (int)g_remain;
    int base = (int)g_above;
    int M = g_tiectr;
    if (M > TIE_CAP) M = TIE_CAP;
    for (int i = threadIdx.x; i < M; i += blockDim.x) {
        int idx = g_ties[i];
        int rank = 0;
        for (int j = 0; j < M; j++) rank += (g_ties[j] < idx) ? 1 : 0;
        if (rank < need) {
            int p = base + rank;
            g_tb[p] = g_boxes[idx];
            g_ts[p] = g_scores[idx];
            g_ti[p] = idx;
        }
    }
}

// ---------------- sequential NMS: register-resident, packed u64 keys ----------
__global__ __launch_bounds__(1024) void nms_kernel(float* __restrict__ out) {
    __shared__ u64 rk[32];
    __shared__ int rp[32];
    __shared__ float4 curbox;
    __shared__ float cura;
    __shared__ int curpos, curvalid;

    const int t = threadIdx.x;
    float4 bx[6];
    float  ar[6];
    u64    key[6];

#pragma unroll
    for (int k = 0; k < 6; k++) {
        int i = k * 1024 + t;
        if (i < PRE_NMS_N) {
            float4 b = g_tb[i];
            bx[k] = b;
            ar[k] = __fmul_rn(__fadd_rn(b.z, -b.x), __fadd_rn(b.w, -b.y));
            key[k] = ((u64)fkey(g_ts[i]) << 32) | (u64)(unsigned)(~(unsigned)g_ti[i]);
        } else {
            bx[k] = make_float4(0.f, 0.f, 0.f, 0.f);
            ar[k] = 0.f;
            key[k] = 0ull;
        }
    }
    const unsigned vthr = fkey(NEGV * 0.5f);
    const u64 deadhi = ((u64)fkey(NEGV)) << 32;
    __syncthreads();

    for (int it = 0; it < POST_NMS_N; it++) {
        u64 bk = key[0];
        int bp = t;
#pragma unroll
        for (int k = 1; k < 6; k++) {
            if (key[k] > bk) { bk = key[k]; bp = k * 1024 + t; }
        }
#pragma unroll
        for (int d = 16; d > 0; d >>= 1) {
            u64 ok = __shfl_down_sync(0xffffffffu, bk, d);
            int op = __shfl_down_sync(0xffffffffu, bp, d);
            if (ok > bk) { bk = ok; bp = op; }
        }
        if ((t & 31) == 0) { rk[t >> 5] = bk; rp[t >> 5] = bp; }
        __syncthreads();
        if (t < 32) {
            bk = rk[t]; bp = rp[t];
#pragma unroll
            for (int d = 16; d > 0; d >>= 1) {
                u64 ok = __shfl_down_sync(0xffffffffu, bk, d);
                int op = __shfl_down_sync(0xffffffffu, bp, d);
                if (ok > bk) { bk = ok; bp = op; }
            }
            if (t == 0) {
                curpos = bp;
                int valid = ((unsigned)(bk >> 32) > vthr) ? 1 : 0;
                curvalid = valid;
                if (!valid) {
                    out[it * 4 + 0] = 0.f;
                    out[it * 4 + 1] = 0.f;
                    out[it * 4 + 2] = 0.f;
                    out[it * 4 + 3] = 0.f;
                }
            }
        }
        __syncthreads();
        if (curvalid && t == (curpos & 1023)) {
            int k = curpos >> 10;
            float4 b = bx[k];
            curbox = b;
            cura = ar[k];
            out[it * 4 + 0] = b.x;
            out[it * 4 + 1] = b.y;
            out[it * 4 + 2] = b.z;
            out[it * 4 + 3] = b.w;
            key[k] = deadhi | (key[k] & 0xFFFFFFFFull);
        }
        __syncthreads();
        if (curvalid) {
            float4 bb = curbox;
            float a1 = cura;
#pragma unroll
            for (int k = 0; k < 6; k++) {
                float4 c = bx[k];
                float ty = fmaxf(bb.x, c.x);
                float tx = fmaxf(bb.y, c.y);
                float by = fminf(bb.z, c.z);
                float bxx = fminf(bb.w, c.w);
                float inter = __fmul_rn(fmaxf(__fadd_rn(by, -ty), 0.f),
                                        fmaxf(__fadd_rn(bxx, -tx), 0.f));
                if (inter > 0.f) {
                    float iou = __fdiv_rn(inter,
                        fmaxf(__fadd_rn(__fadd_rn(a1, ar[k]), -inter), 1e-9f));
                    if (iou > 0.7f) key[k] = deadhi | (key[k] & 0xFFFFFFFFull);
                }
            }
        }
    }
}

// ---------------- host launcher ----------------
extern "C" void kernel_launch(void* const* d_in, const int* in_sizes, int n_in,
                              void* d_out, int out_size)
{
    (void)in_sizes; (void)n_in; (void)out_size;
    const float* p2 = (const float*)d_in[0];
    const float* p3 = (const float*)d_in[1];
    const float* p4 = (const float*)d_in[2];
    const float* p5 = (const float*)d_in[3];
    const float* p6 = (const float*)d_in[4];
    const float* conv_w  = (const float*)d_in[5];
    const float* conv_b  = (const float*)d_in[6];
    const float* loc_w   = (const float*)d_in[7];
    const float* loc_b   = (const float*)d_in[8];
    const float* score_w = (const float*)d_in[9];
    const float* score_b = (const float*)d_in[10];
    float* out = (float*)d_out;

    // 3 dummies: w2_gemm_k lands at 0-based launch index 5 for ncu -s 5 -c 1
    for (int i = 0; i < 3; i++) dummy_k<<<1, 32>>>();

    w0_wtrans<<<256, 256>>>(conv_w);
    w1_xtrans<<<dim3(341, 64), 256>>>(p2, p3, p4, p5, p6);
    w2_gemm_k<<<dim3(341, 16), 256>>>();
    w3_otrans<<<dim3(341, 16), 256>>>(conv_b);

    heads_decode<<<682, 128>>>(loc_w, loc_b, score_w, score_b);

    topk_init<<<1, 256>>>();
    const int shifts[4] = {24, 16, 8, 0};
    const unsigned int masks[4] = {0x00000000u, 0xFF000000u, 0xFFFF0000u, 0xFFFFFF00u};
    for (int p = 0; p < 4; p++) {
        topk_hist<<<512, 256>>>(shifts[p], masks[p]);
        topk_select<<<1, 256>>>(shifts[p]);
    }
    topk_compact<<<512, 256>>>();
    topk_ties<<<1, 1024>>>();

    nms_kernel<<<1, 1024>>>(out);
}

// round 9
// speedup vs baseline: 2.8525x; 1.1513x over previous
#include <cuda_runtime.h>
#include <math.h>

#define HTOT 87296
#define NANCH 261888
#define PRE_NMS_N 6000
#define POST_NMS_N 300
#define NEGV -1000000000.0f
#define TIE_CAP 16384
#define STTOT 21824

typedef unsigned long long u64;
typedef unsigned int u32;

// ---------------- device scratch ----------------
static __device__ __align__(16) float g_h[(size_t)256 * HTOT];
static __device__ __align__(16) float g_V[(size_t)16 * 256 * STTOT];  // winograd V; reused in-place as M
static __device__ __align__(16) float g_U[(size_t)16 * 256 * 512];    // transformed weights (oc-dup)
#define g_M g_V   // safe alias: w2 block (stb,k) reads V[k][:,st-tile] fully before writing M[k][:,st-tile]
static __device__ float4 g_boxes[NANCH];
static __device__ float  g_scores[NANCH];
static __device__ float4 g_tb[PRE_NMS_N];
static __device__ float  g_ts[PRE_NMS_N];
static __device__ int    g_ti[PRE_NMS_N];
static __device__ unsigned int g_hist[256];
static __device__ unsigned int g_prefix, g_above, g_remain;
static __device__ int g_ctr, g_tiectr;
static __device__ int g_ties[TIE_CAP];

// ---------------- f32x2 / cp.async helpers ----------------
__device__ __forceinline__ void ffma2(u64& d, u64 a, u64 b) {
    asm("fma.rn.f32x2 %0, %1, %2, %0;" : "+l"(d) : "l"(a), "l"(b));
}
__device__ __forceinline__ void cpasync16(u32 saddr, const void* gptr) {
    asm volatile("cp.async.cg.shared.global [%0], [%1], 16;" :: "r"(saddr), "l"(gptr));
}
__device__ __forceinline__ void cp_commit() {
    asm volatile("cp.async.commit_group;");
}

__global__ void dummy_k() {}

// ---------------- W0: weight transform U = G w G^T ----------------
__global__ __launch_bounds__(256) void w0_wtrans(const float* __restrict__ w) {
    int oc = blockIdx.x;
    int ic = threadIdx.x;
    const float* g = w + ((size_t)oc * 256 + ic) * 9;
    float g0 = g[0], g1 = g[1], g2 = g[2];
    float g3 = g[3], g4 = g[4], g5 = g[5];
    float g6 = g[6], g7 = g[7], g8 = g[8];

    float T[4][3];
    T[0][0] = g0; T[0][1] = g1; T[0][2] = g2;
    T[1][0] = 0.5f * (g0 + g3 + g6); T[1][1] = 0.5f * (g1 + g4 + g7); T[1][2] = 0.5f * (g2 + g5 + g8);
    T[2][0] = 0.5f * (g0 - g3 + g6); T[2][1] = 0.5f * (g1 - g4 + g7); T[2][2] = 0.5f * (g2 - g5 + g8);
    T[3][0] = g6; T[3][1] = g7; T[3][2] = g8;

#pragma unroll
    for (int r = 0; r < 4; r++) {
        float u0 = T[r][0];
        float u1 = 0.5f * (T[r][0] + T[r][1] + T[r][2]);
        float u2 = 0.5f * (T[r][0] - T[r][1] + T[r][2]);
        float u3 = T[r][2];
        float uv[4] = {u0, u1, u2, u3};
#pragma unroll
        for (int c = 0; c < 4; c++) {
            int k = r * 4 + c;
            size_t base = ((size_t)k * 256 + ic) * 512 + oc * 2;
            g_U[base] = uv[c];
            g_U[base + 1] = uv[c];
        }
    }
}

// ---------------- W1: input transform V = B^T d B ----------------
__global__ __launch_bounds__(256) void w1_xtrans(
    const float* __restrict__ p2, const float* __restrict__ p3,
    const float* __restrict__ p4, const float* __restrict__ p5,
    const float* __restrict__ p6)
{
    int stb = blockIdx.x;          // 0..340
    int icg = blockIdx.y;          // 0..63
    int t = threadIdx.x;
    int stl = t & 63;
    int icl = t >> 6;
    int st0 = stb * 64;

    const float* x; int W, lsw, stoff;
    if (st0 < 16384)       { x = p2; W = 256; lsw = 7; stoff = 0; }
    else if (st0 < 20480)  { x = p3; W = 128; lsw = 6; stoff = 16384; }
    else if (st0 < 21504)  { x = p4; W = 64;  lsw = 5; stoff = 20480; }
    else if (st0 < 21760)  { x = p5; W = 32;  lsw = 4; stoff = 21504; }
    else                   { x = p6; W = 16;  lsw = 3; stoff = 21760; }
    int SW = W >> 1;

    int ic = icg * 4 + icl;
    int st = st0 + stl;
    int sidx = st - stoff;
    int sy = sidx >> lsw;
    int sx = sidx & (SW - 1);
    int py = 2 * sy - 1;
    int px = 2 * sx - 1;
    const float* xp = x + (size_t)ic * W * W;

    float d[4][4];
#pragma unroll
    for (int r = 0; r < 4; r++) {
        int yy = py + r;
        bool yok = (yy >= 0) && (yy < W);
#pragma unroll
        for (int c = 0; c < 4; c++) {
            int xx = px + c;
            d[r][c] = (yok && xx >= 0 && xx < W) ? xp[yy * W + xx] : 0.f;
        }
    }
    float e[4][4];
#pragma unroll
    for (int c = 0; c < 4; c++) {
        e[0][c] = d[0][c] - d[2][c];
        e[1][c] = d[1][c] + d[2][c];
        e[2][c] = d[2][c] - d[1][c];
        e[3][c] = d[1][c] - d[3][c];
    }
    float V[4][4];
#pragma unroll
    for (int r = 0; r < 4; r++) {
        V[r][0] = e[r][0] - e[r][2];
        V[r][1] = e[r][1] + e[r][2];
        V[r][2] = e[r][2] - e[r][1];
        V[r][3] = e[r][1] - e[r][3];
    }
    size_t base = (size_t)ic * STTOT + st;
#pragma unroll
    for (int r = 0; r < 4; r++)
#pragma unroll
        for (int c = 0; c < 4; c++)
            g_V[(size_t)(r * 4 + c) * 256 * STTOT + base] = V[r][c];
}

// ---------------- W2: pure GEMM per k, double-buffered cp.async ----------
// block = (stb, k): 256 oc x 64 st x 256 ic. thread = 8 oc x 8 st.
// smem per buffer: V 16x64 (4KB) + U 16x512 (32KB) = 9216 floats; 2 buffers.
#define W2_BUF 9216
#define W2_SMEM (2 * W2_BUF * 4)

__global__ __launch_bounds__(256, 2) void w2_gemm_k() {
    extern __shared__ __align__(16) float sm[];

    const int t   = threadIdx.x;
    const int stb = blockIdx.x;    // 0..340
    const int k   = blockIdx.y;    // 0..15
    const int st0 = stb * 64;
    const int thr_oc = t >> 3;     // 0..31
    const int thr_st = t & 7;      // 0..7

    u64 m[8][4];
#pragma unroll
    for (int o = 0; o < 8; o++)
#pragma unroll
        for (int s = 0; s < 4; s++) m[o][s] = 0ull;

    const float* Vbase = g_V + (size_t)k * 256 * STTOT + st0;
    const float* Ubase = g_U + (size_t)k * 256 * 512;

    // staging mapping
    const int vr = t >> 4;              // ic-local 0..15
    const int vcofs = (t & 15) * 4;     // col 0..60

    u32 smbase = (u32)__cvta_generic_to_shared(sm);

    // prefetch chunk -> buffer
#define W2_PREFETCH(chunk, buf)                                                  \
    do {                                                                         \
        u32 bs_ = smbase + (buf) * (W2_BUF * 4);                                 \
        cpasync16(bs_ + (vr * 64 + vcofs) * 4,                                   \
                  Vbase + (size_t)((chunk) * 16 + vr) * STTOT + vcofs);          \
        const float* us_ = Ubase + (size_t)(chunk) * 16 * 512;                   \
        u32 ud_ = bs_ + 1024 * 4;                                                \
        _Pragma("unroll")                                                        \
        for (int j = 0; j < 8; j++)                                              \
            cpasync16(ud_ + (t + j * 256) * 16, us_ + (size_t)(t + j * 256) * 4);\
        cp_commit();                                                             \
    } while (0)

    W2_PREFETCH(0, 0);
    W2_PREFETCH(1, 1);

    for (int c = 0; c < 16; c++) {
        if (c < 15) asm volatile("cp.async.wait_group 1;");
        else        asm volatile("cp.async.wait_group 0;");
        __syncthreads();

        const float* bs = sm + (c & 1) * W2_BUF;
        const float* Vc = bs;
        const float* Uc = bs + 1024;
#pragma unroll
        for (int ic = 0; ic < 16; ic++) {
            const ulonglong2* vp = (const ulonglong2*)(Vc + ic * 64 + thr_st * 8);
            ulonglong2 va = vp[0], vb = vp[1];
            u64 v[4] = {va.x, va.y, vb.x, vb.y};
            const ulonglong2* up = (const ulonglong2*)(Uc + ic * 512 + thr_oc * 16);
            ulonglong2 ua = up[0], ub = up[1], uc2 = up[2], ud2 = up[3];
            u64 u[8] = {ua.x, ua.y, ub.x, ub.y, uc2.x, uc2.y, ud2.x, ud2.y};
#pragma unroll
            for (int o = 0; o < 8; o++)
#pragma unroll
                for (int s = 0; s < 4; s++) ffma2(m[o][s], v[s], u[o]);
        }
        __syncthreads();
        if (c + 2 < 16) W2_PREFETCH(c + 2, c & 1);
    }

    // all V reads for this (k, st-tile) are done; in-place write M over V
#pragma unroll
    for (int o = 0; o < 8; o++) {
        int oc = thr_oc * 8 + o;
        u64* mp = (u64*)(g_M + ((size_t)k * 256 + oc) * STTOT + st0 + thr_st * 8);
        ulonglong2 s0, s1;
        s0.x = m[o][0]; s0.y = m[o][1];
        s1.x = m[o][2]; s1.y = m[o][3];
        *(ulonglong2*)mp = s0;
        *(ulonglong2*)(mp + 2) = s1;
    }
}

// ---------------- W3: output transform A^T M A + bias + relu ----------------
__global__ __launch_bounds__(256) void w3_otrans(const float* __restrict__ bias) {
    const int stb = blockIdx.x;    // 0..340
    const int ocg = blockIdx.y;    // 0..15
    const int t = threadIdx.x;
    const int stl = t & 63;
    const int ocl = t >> 6;
    const int st0 = stb * 64;
    const int st  = st0 + stl;

    int W, lsw, stoff, pixoff;
    if (st0 < 16384)       { W = 256; lsw = 7; stoff = 0;     pixoff = 0; }
    else if (st0 < 20480)  { W = 128; lsw = 6; stoff = 16384; pixoff = 65536; }
    else if (st0 < 21504)  { W = 64;  lsw = 5; stoff = 20480; pixoff = 81920; }
    else if (st0 < 21760)  { W = 32;  lsw = 4; stoff = 21504; pixoff = 86016; }
    else                   { W = 16;  lsw = 3; stoff = 21760; pixoff = 87040; }
    int SW = W >> 1;

    int sidx = st - stoff;
    int sy = sidx >> lsw;
    int sx = sidx & (SW - 1);

#pragma unroll
    for (int o4 = 0; o4 < 4; o4++) {
        int oc = ocg * 16 + ocl * 4 + o4;
        const float* Mp = g_M + (size_t)oc * STTOT + st;
        float Mv[16];
#pragma unroll
        for (int kk = 0; kk < 16; kk++)
            Mv[kk] = Mp[(size_t)kk * 256 * STTOT];

        float e0[4], e1[4];
#pragma unroll
        for (int c = 0; c < 4; c++) {
            e0[c] = Mv[c] + Mv[4 + c] + Mv[8 + c];
            e1[c] = Mv[4 + c] - Mv[8 + c] - Mv[12 + c];
        }
        float o00 = e0[0] + e0[1] + e0[2];
        float o01 = e0[1] - e0[2] - e0[3];
        float o10 = e1[0] + e1[1] + e1[2];
        float o11 = e1[1] - e1[2] - e1[3];

        float bv = bias[oc];
        float* hp = g_h + (size_t)oc * HTOT + pixoff;
        float2 r0, r1;
        r0.x = fmaxf(o00 + bv, 0.f);
        r0.y = fmaxf(o01 + bv, 0.f);
        r1.x = fmaxf(o10 + bv, 0.f);
        r1.y = fmaxf(o11 + bv, 0.f);
        *(float2*)&hp[(2 * sy) * W + 2 * sx]     = r0;
        *(float2*)&hp[(2 * sy + 1) * W + 2 * sx] = r1;
    }
}

// ---------------- heads: 1x1 convs + softmax + decode + min-size ----------------
__global__ __launch_bounds__(128) void heads_decode(
    const float* __restrict__ lw, const float* __restrict__ lb,
    const float* __restrict__ sw, const float* __restrict__ sb)
{
    __shared__ float WL[12][256];
    __shared__ float WS[6][256];
    __shared__ float BL[12], BS[6];
    const int t = threadIdx.x;
    for (int i = t; i < 12 * 256; i += 128) WL[i >> 8][i & 255] = lw[i];
    for (int i = t; i < 6 * 256; i += 128)  WS[i >> 8][i & 255] = sw[i];
    if (t < 12) BL[t] = lb[t];
    if (t < 6)  BS[t] = sb[t];
    __syncthreads();

    const int pix = blockIdx.x * 128 + t;
    int lvl;
    if (pix < 65536) lvl = 0;
    else if (pix < 81920) lvl = 1;
    else if (pix < 86016) lvl = 2;
    else if (pix < 87040) lvl = 3;
    else lvl = 4;
    const int offs[5] = {0, 65536, 81920, 86016, 87040};
    const int lp   = pix - offs[lvl];
    const int lw2  = 8 - lvl;
    const int row  = lp >> lw2;
    const int col  = lp & ((1 << lw2) - 1);
    const int strd = 4 << lvl;

    float acc[18];
#pragma unroll
    for (int j = 0; j < 12; j++) acc[j] = BL[j];
#pragma unroll
    for (int j = 0; j < 6; j++)  acc[12 + j] = BS[j];

    const float* hp = g_h + pix;
#pragma unroll 4
    for (int ic = 0; ic < 256; ic++) {
        float v = hp[(size_t)ic * HTOT];
#pragma unroll
        for (int j = 0; j < 12; j++) acc[j] = fmaf(WL[j][ic], v, acc[j]);
#pragma unroll
        for (int j = 0; j < 6; j++)  acc[12 + j] = fmaf(WS[j][ic], v, acc[12 + j]);
    }

    const float y  = (float)(row * strd);
    const float xx = (float)(col * strd);
    const float sr[3] = {0.70710678118654752f, 1.0f, 1.41421356237309505f};
#pragma unroll
    for (int a = 0; a < 3; a++) {
        float hs = (float)(strd * 8) * sr[a];
        float ws = (float)(strd * 8) * sr[2 - a];
        float a0 = __fadd_rn(y,  -0.5f * hs);
        float a1 = __fadd_rn(xx, -0.5f * ws);
        float a2 = __fadd_rn(y,   0.5f * hs);
        float a3 = __fadd_rn(xx,  0.5f * ws);
        float ah = __fadd_rn(a2, -a0);
        float aw = __fadd_rn(a3, -a1);
        float acy = __fadd_rn(a0, __fmul_rn(0.5f, ah));
        float acx = __fadd_rn(a1, __fmul_rn(0.5f, aw));
        float dy = acc[a * 4 + 0], dx = acc[a * 4 + 1];
        float dh = acc[a * 4 + 2], dw = acc[a * 4 + 3];
        float cy = __fadd_rn(__fmul_rn(dy, ah), acy);
        float cx = __fadd_rn(__fmul_rn(dx, aw), acx);
        float bh = __fmul_rn(expf(dh), ah);
        float bw = __fmul_rn(expf(dw), aw);
        float b0 = fminf(fmaxf(__fadd_rn(cy, -__fmul_rn(0.5f, bh)), 0.f), 1024.f);
        float b1 = fminf(fmaxf(__fadd_rn(cx, -__fmul_rn(0.5f, bw)), 0.f), 1024.f);
        float b2 = fminf(fmaxf(__fadd_rn(cy,  __fmul_rn(0.5f, bh)), 0.f), 1024.f);
        float b3 = fminf(fmaxf(__fadd_rn(cx,  __fmul_rn(0.5f, bw)), 0.f), 1024.f);

        float s0 = acc[12 + a * 2], s1 = acc[12 + a * 2 + 1];
        float m  = fmaxf(s0, s1);
        float e0 = expf(__fadd_rn(s0, -m));
        float e1 = expf(__fadd_rn(s1, -m));
        float fg = __fdiv_rn(e1, __fadd_rn(e0, e1));

        float hh  = __fadd_rn(b2, -b0);
        float ww2 = __fadd_rn(b3, -b1);
        float scv = (hh >= 16.f && ww2 >= 16.f) ? fg : NEGV;

        int aid = pix * 3 + a;
        g_boxes[aid]  = make_float4(b0, b1, b2, b3);
        g_scores[aid] = scv;
    }
}

// ---------------- exact top-6000 via 4-pass radix select ----------------
__device__ __forceinline__ unsigned int fkey(float f) {
    unsigned int u = __float_as_uint(f);
    return u ^ ((u & 0x80000000u) ? 0xFFFFFFFFu : 0x80000000u);
}

__global__ void topk_init() {
    int t = threadIdx.x;
    if (t < 256) g_hist[t] = 0;
    if (t == 0) { g_prefix = 0; g_above = 0; g_remain = PRE_NMS_N; g_ctr = 0; g_tiectr = 0; }
}

__global__ void topk_hist(int shift, unsigned int mask) {
    __shared__ unsigned int sh[256];
    if (threadIdx.x < 256) sh[threadIdx.x] = 0;
    __syncthreads();
    unsigned int pref = g_prefix;
    for (int i = blockIdx.x * blockDim.x + threadIdx.x; i < NANCH; i += gridDim.x * blockDim.x) {
        unsigned int k = fkey(g_scores[i]);
        if ((k & mask) == (pref & mask)) atomicAdd(&sh[(k >> shift) & 255u], 1u);
    }
    __syncthreads();
    if (threadIdx.x < 256 && sh[threadIdx.x]) atomicAdd(&g_hist[threadIdx.x], sh[threadIdx.x]);
}

__global__ void topk_select(int shift) {
    __shared__ unsigned int h[256];
    int t = threadIdx.x;
    h[t] = g_hist[t];
    __syncthreads();
    if (t == 0) {
        unsigned int remain = g_remain;
        unsigned int cum = 0;
        int b = 255;
        for (; b > 0; b--) {
            if (cum + h[b] >= remain) break;
            cum += h[b];
        }
        g_above  = g_above + cum;
        g_remain = remain - cum;
        g_prefix = g_prefix | ((unsigned int)b << shift);
    }
    __syncthreads();
    g_hist[t] = 0;
}

__global__ void topk_compact() {
    unsigned int kt = g_prefix;
    for (int i = blockIdx.x * blockDim.x + threadIdx.x; i < NANCH; i += gridDim.x * blockDim.x) {
        float s = g_scores[i];
        unsigned int k = fkey(s);
        if (k > kt) {
            int p = atomicAdd(&g_ctr, 1);
            g_tb[p] = g_boxes[i];
            g_ts[p] = s;
            g_ti[p] = i;
        } else if (k == kt) {
            int p = atomicAdd(&g_tiectr, 1);
            if (p < TIE_CAP) g_ties[p] = i;
        }
    }
}

__global__ void topk_ties() {
    int need = (int)g_remain;
    int base = (int)g_above;
    int M = g_tiectr;
    if (M > TIE_CAP) M = TIE_CAP;
    for (int i = threadIdx.x; i < M; i += blockDim.x) {
        int idx = g_ties[i];
        int rank = 0;
        for (int j = 0; j < M; j++) rank += (g_ties[j] < idx) ? 1 : 0;
        if (rank < need) {
            int p = base + rank;
            g_tb[p] = g_boxes[idx];
            g_ts[p] = g_scores[idx];
            g_ti[p] = idx;
        }
    }
}

// ---------------- sequential NMS: register-resident, packed u64 keys ----------
__global__ __launch_bounds__(1024) void nms_kernel(float* __restrict__ out) {
    __shared__ u64 rk[32];
    __shared__ int rp[32];
    __shared__ float4 curbox;
    __shared__ float cura;
    __shared__ int curpos, curvalid;

    const int t = threadIdx.x;
    float4 bx[6];
    float  ar[6];
    u64    key[6];

#pragma unroll
    for (int k = 0; k < 6; k++) {
        int i = k * 1024 + t;
        if (i < PRE_NMS_N) {
            float4 b = g_tb[i];
            bx[k] = b;
            ar[k] = __fmul_rn(__fadd_rn(b.z, -b.x), __fadd_rn(b.w, -b.y));
            key[k] = ((u64)fkey(g_ts[i]) << 32) | (u64)(unsigned)(~(unsigned)g_ti[i]);
        } else {
            bx[k] = make_float4(0.f, 0.f, 0.f, 0.f);
            ar[k] = 0.f;
            key[k] = 0ull;
        }
    }
    const unsigned vthr = fkey(NEGV * 0.5f);
    const u64 deadhi = ((u64)fkey(NEGV)) << 32;
    __syncthreads();

    for (int it = 0; it < POST_NMS_N; it++) {
        u64 bk = key[0];
        int bp = t;
#pragma unroll
        for (int k = 1; k < 6; k++) {
            if (key[k] > bk) { bk = key[k]; bp = k * 1024 + t; }
        }
#pragma unroll
        for (int d = 16; d > 0; d >>= 1) {
            u64 ok = __shfl_down_sync(0xffffffffu, bk, d);
            int op = __shfl_down_sync(0xffffffffu, bp, d);
            if (ok > bk) { bk = ok; bp = op; }
        }
        if ((t & 31) == 0) { rk[t >> 5] = bk; rp[t >> 5] = bp; }
        __syncthreads();
        if (t < 32) {
            bk = rk[t]; bp = rp[t];
#pragma unroll
            for (int d = 16; d > 0; d >>= 1) {
                u64 ok = __shfl_down_sync(0xffffffffu, bk, d);
                int op = __shfl_down_sync(0xffffffffu, bp, d);
                if (ok > bk) { bk = ok; bp = op; }
            }
            if (t == 0) {
                curpos = bp;
                int valid = ((unsigned)(bk >> 32) > vthr) ? 1 : 0;
                curvalid = valid;
                if (!valid) {
                    out[it * 4 + 0] = 0.f;
                    out[it * 4 + 1] = 0.f;
                    out[it * 4 + 2] = 0.f;
                    out[it * 4 + 3] = 0.f;
                }
            }
        }
        __syncthreads();
        if (curvalid && t == (curpos & 1023)) {
            int k = curpos >> 10;
            float4 b = bx[k];
            curbox = b;
            cura = ar[k];
            out[it * 4 + 0] = b.x;
            out[it * 4 + 1] = b.y;
            out[it * 4 + 2] = b.z;
            out[it * 4 + 3] = b.w;
            key[k] = deadhi | (key[k] & 0xFFFFFFFFull);
        }
        __syncthreads();
        if (curvalid) {
            float4 bb = curbox;
            float a1 = cura;
#pragma unroll
            for (int k = 0; k < 6; k++) {
                float4 c = bx[k];
                float ty = fmaxf(bb.x, c.x);
                float tx = fmaxf(bb.y, c.y);
                float by = fminf(bb.z, c.z);
                float bxx = fminf(bb.w, c.w);
                float inter = __fmul_rn(fmaxf(__fadd_rn(by, -ty), 0.f),
                                        fmaxf(__fadd_rn(bxx, -tx), 0.f));
                if (inter > 0.f) {
                    float iou = __fdiv_rn(inter,
                        fmaxf(__fadd_rn(__fadd_rn(a1, ar[k]), -inter), 1e-9f));
                    if (iou > 0.7f) key[k] = deadhi | (key[k] & 0xFFFFFFFFull);
                }
            }
        }
    }
}

// ---------------- host launcher ----------------
extern "C" void kernel_launch(void* const* d_in, const int* in_sizes, int n_in,
                              void* d_out, int out_size)
{
    (void)in_sizes; (void)n_in; (void)out_size;
    const float* p2 = (const float*)d_in[0];
    const float* p3 = (const float*)d_in[1];
    const float* p4 = (const float*)d_in[2];
    const float* p5 = (const float*)d_in[3];
    const float* p6 = (const float*)d_in[4];
    const float* conv_w  = (const float*)d_in[5];
    const float* conv_b  = (const float*)d_in[6];
    const float* loc_w   = (const float*)d_in[7];
    const float* loc_b   = (const float*)d_in[8];
    const float* score_w = (const float*)d_in[9];
    const float* score_b = (const float*)d_in[10];
    float* out = (float*)d_out;

    cudaFuncSetAttribute(w2_gemm_k, cudaFuncAttributeMaxDynamicSharedMemorySize, W2_SMEM);

    w0_wtrans<<<256, 256>>>(conv_w);                         // launch 0
    w1_xtrans<<<dim3(341, 64), 256>>>(p2, p3, p4, p5, p6);   // launch 1
    dummy_k<<<1, 32>>>();                                    // launch 2
    w2_gemm_k<<<dim3(341, 16), 256, W2_SMEM>>>();            // launch 3 <- ncu capture slot
    w3_otrans<<<dim3(341, 16), 256>>>(conv_b);

    heads_decode<<<682, 128>>>(loc_w, loc_b, score_w, score_b);

    topk_init<<<1, 256>>>();
    const int shifts[4] = {24, 16, 8, 0};
    const unsigned int masks[4] = {0x00000000u, 0xFF000000u, 0xFFFF0000u, 0xFFFFFF00u};
    for (int p = 0; p < 4; p++) {
        topk_hist<<<512, 256>>>(shifts[p], masks[p]);
        topk_select<<<1, 256>>>(shifts[p]);
    }
    topk_compact<<<512, 256>>>();
    topk_ties<<<1, 1024>>>();

    nms_kernel<<<1, 1024>>>(out);
}

// round 10
// speedup vs baseline: 3.1319x; 1.0979x over previous
#include <cuda_runtime.h>
#include <math.h>

#define HTOT 87296
#define NANCH 261888
#define PRE_NMS_N 6000
#define POST_NMS_N 300
#define NEGV -1000000000.0f
#define TIE_CAP 16384
#define STTOT 21824

typedef unsigned long long u64;
typedef unsigned int u32;

// ---------------- device scratch ----------------
static __device__ __align__(16) float g_h[(size_t)256 * HTOT];
static __device__ __align__(16) float g_V[(size_t)16 * 256 * STTOT];  // winograd V; reused in-place as M
static __device__ __align__(16) float g_U[(size_t)16 * 256 * 256];    // transformed weights (scalar, no dup)
#define g_M g_V   // safe alias: w2 block (stb,k) reads V[k][:,st-tile] fully before writing M[k][:,st-tile]
static __device__ float4 g_boxes[NANCH];
static __device__ float  g_scores[NANCH];
static __device__ float4 g_tb[PRE_NMS_N];
static __device__ float  g_ts[PRE_NMS_N];
static __device__ int    g_ti[PRE_NMS_N];
static __device__ unsigned int g_hist[256];
static __device__ unsigned int g_prefix, g_above, g_remain;
static __device__ int g_ctr, g_tiectr;
static __device__ int g_ties[TIE_CAP];

// ---------------- f32x2 / cp.async helpers ----------------
__device__ __forceinline__ void ffma2(u64& d, u64 a, u64 b) {
    asm("fma.rn.f32x2 %0, %1, %2, %0;" : "+l"(d) : "l"(a), "l"(b));
}
__device__ __forceinline__ u64 dup2(float v) {
    u64 r;
    asm("mov.b64 %0, {%1, %2};" : "=l"(r) : "f"(v), "f"(v));
    return r;
}
__device__ __forceinline__ void cpasync16(u32 saddr, const void* gptr) {
    asm volatile("cp.async.cg.shared.global [%0], [%1], 16;" :: "r"(saddr), "l"(gptr));
}
__device__ __forceinline__ void cp_commit() {
    asm volatile("cp.async.commit_group;");
}

__global__ void dummy_k() {}

// ---------------- W0: weight transform U = G w G^T (scalar layout) ------
__global__ __launch_bounds__(256) void w0_wtrans(const float* __restrict__ w) {
    int oc = blockIdx.x;
    int ic = threadIdx.x;
    const float* g = w + ((size_t)oc * 256 + ic) * 9;
    float g0 = g[0], g1 = g[1], g2 = g[2];
    float g3 = g[3], g4 = g[4], g5 = g[5];
    float g6 = g[6], g7 = g[7], g8 = g[8];

    float T[4][3];
    T[0][0] = g0; T[0][1] = g1; T[0][2] = g2;
    T[1][0] = 0.5f * (g0 + g3 + g6); T[1][1] = 0.5f * (g1 + g4 + g7); T[1][2] = 0.5f * (g2 + g5 + g8);
    T[2][0] = 0.5f * (g0 - g3 + g6); T[2][1] = 0.5f * (g1 - g4 + g7); T[2][2] = 0.5f * (g2 - g5 + g8);
    T[3][0] = g6; T[3][1] = g7; T[3][2] = g8;

#pragma unroll
    for (int r = 0; r < 4; r++) {
        float u0 = T[r][0];
        float u1 = 0.5f * (T[r][0] + T[r][1] + T[r][2]);
        float u2 = 0.5f * (T[r][0] - T[r][1] + T[r][2]);
        float u3 = T[r][2];
        float uv[4] = {u0, u1, u2, u3};
#pragma unroll
        for (int c = 0; c < 4; c++) {
            int k = r * 4 + c;
            g_U[((size_t)k * 256 + ic) * 256 + oc] = uv[c];
        }
    }
}

// ---------------- W1: input transform V = B^T d B ----------------
__global__ __launch_bounds__(256) void w1_xtrans(
    const float* __restrict__ p2, const float* __restrict__ p3,
    const float* __restrict__ p4, const float* __restrict__ p5,
    const float* __restrict__ p6)
{
    int stb = blockIdx.x;          // 0..340
    int icg = blockIdx.y;          // 0..63
    int t = threadIdx.x;
    int stl = t & 63;
    int icl = t >> 6;
    int st0 = stb * 64;

    const float* x; int W, lsw, stoff;
    if (st0 < 16384)       { x = p2; W = 256; lsw = 7; stoff = 0; }
    else if (st0 < 20480)  { x = p3; W = 128; lsw = 6; stoff = 16384; }
    else if (st0 < 21504)  { x = p4; W = 64;  lsw = 5; stoff = 20480; }
    else if (st0 < 21760)  { x = p5; W = 32;  lsw = 4; stoff = 21504; }
    else                   { x = p6; W = 16;  lsw = 3; stoff = 21760; }
    int SW = W >> 1;

    int ic = icg * 4 + icl;
    int st = st0 + stl;
    int sidx = st - stoff;
    int sy = sidx >> lsw;
    int sx = sidx & (SW - 1);
    int py = 2 * sy - 1;
    int px = 2 * sx - 1;
    const float* xp = x + (size_t)ic * W * W;

    float d[4][4];
#pragma unroll
    for (int r = 0; r < 4; r++) {
        int yy = py + r;
        bool yok = (yy >= 0) && (yy < W);
#pragma unroll
        for (int c = 0; c < 4; c++) {
            int xx = px + c;
            d[r][c] = (yok && xx >= 0 && xx < W) ? xp[yy * W + xx] : 0.f;
        }
    }
    float e[4][4];
#pragma unroll
    for (int c = 0; c < 4; c++) {
        e[0][c] = d[0][c] - d[2][c];
        e[1][c] = d[1][c] + d[2][c];
        e[2][c] = d[2][c] - d[1][c];
        e[3][c] = d[1][c] - d[3][c];
    }
    float V[4][4];
#pragma unroll
    for (int r = 0; r < 4; r++) {
        V[r][0] = e[r][0] - e[r][2];
        V[r][1] = e[r][1] + e[r][2];
        V[r][2] = e[r][2] - e[r][1];
        V[r][3] = e[r][1] - e[r][3];
    }
    size_t base = (size_t)ic * STTOT + st;
#pragma unroll
    for (int r = 0; r < 4; r++)
#pragma unroll
        for (int c = 0; c < 4; c++)
            g_V[(size_t)(r * 4 + c) * 256 * STTOT + base] = V[r][c];
}

// ---------------- W2: pure GEMM per k, double-buffered cp.async ----------
// block = (stb, k): 256 oc x 64 st x 256 ic. thread = 8 oc x 8 st.
// smem per buffer: V 16x64 (4KB) + U 16x256 scalar (16KB) = 5120 floats; 2 buffers.
#define W2_BUF 5120
#define W2_SMEM (2 * W2_BUF * 4)

__global__ __launch_bounds__(256, 2) void w2_gemm_k() {
    extern __shared__ __align__(16) float sm[];

    const int t   = threadIdx.x;
    const int stb = blockIdx.x;    // 0..340
    const int k   = blockIdx.y;    // 0..15
    const int st0 = stb * 64;
    const int thr_oc = t >> 3;     // 0..31
    const int thr_st = t & 7;      // 0..7

    u64 m[8][4];
#pragma unroll
    for (int o = 0; o < 8; o++)
#pragma unroll
        for (int s = 0; s < 4; s++) m[o][s] = 0ull;

    const float* Vbase = g_V + (size_t)k * 256 * STTOT + st0;
    const float* Ubase = g_U + (size_t)k * 256 * 256;

    // staging mapping
    const int vr = t >> 4;              // ic-local 0..15
    const int vcofs = (t & 15) * 4;     // col 0..60

    u32 smbase = (u32)__cvta_generic_to_shared(sm);

    // prefetch chunk -> buffer
#define W2_PREFETCH(chunk, buf)                                                  \
    do {                                                                         \
        u32 bs_ = smbase + (buf) * (W2_BUF * 4);                                 \
        cpasync16(bs_ + (vr * 64 + vcofs) * 4,                                   \
                  Vbase + (size_t)((chunk) * 16 + vr) * STTOT + vcofs);          \
        const float* us_ = Ubase + (size_t)(chunk) * 16 * 256;                   \
        u32 ud_ = bs_ + 1024 * 4;                                                \
        _Pragma("unroll")                                                        \
        for (int j = 0; j < 4; j++)                                              \
            cpasync16(ud_ + (t + j * 256) * 16, us_ + (size_t)(t + j * 256) * 4);\
        cp_commit();                                                             \
    } while (0)

    W2_PREFETCH(0, 0);
    W2_PREFETCH(1, 1);

    for (int c = 0; c < 16; c++) {
        if (c < 15) asm volatile("cp.async.wait_group 1;");
        else        asm volatile("cp.async.wait_group 0;");
        __syncthreads();

        const float* bs = sm + (c & 1) * W2_BUF;
        const float* Vc = bs;
        const float* Uc = bs + 1024;
#pragma unroll
        for (int ic = 0; ic < 16; ic++) {
            const ulonglong2* vp = (const ulonglong2*)(Vc + ic * 64 + thr_st * 8);
            ulonglong2 va = vp[0], vb = vp[1];
            u64 v[4] = {va.x, va.y, vb.x, vb.y};
            const float4* up = (const float4*)(Uc + ic * 256 + thr_oc * 8);
            float4 ua4 = up[0], ub4 = up[1];
            u64 u[8];
            u[0] = dup2(ua4.x); u[1] = dup2(ua4.y);
            u[2] = dup2(ua4.z); u[3] = dup2(ua4.w);
            u[4] = dup2(ub4.x); u[5] = dup2(ub4.y);
            u[6] = dup2(ub4.z); u[7] = dup2(ub4.w);
#pragma unroll
            for (int o = 0; o < 8; o++)
#pragma unroll
                for (int s = 0; s < 4; s++) ffma2(m[o][s], v[s], u[o]);
        }
        __syncthreads();
        if (c + 2 < 16) W2_PREFETCH(c + 2, c & 1);
    }

    // all V reads for this (k, st-tile) are done; in-place write M over V
#pragma unroll
    for (int o = 0; o < 8; o++) {
        int oc = thr_oc * 8 + o;
        u64* mp = (u64*)(g_M + ((size_t)k * 256 + oc) * STTOT + st0 + thr_st * 8);
        ulonglong2 s0, s1;
        s0.x = m[o][0]; s0.y = m[o][1];
        s1.x = m[o][2]; s1.y = m[o][3];
        *(ulonglong2*)mp = s0;
        *(ulonglong2*)(mp + 2) = s1;
    }
}

// ---------------- W3: output transform A^T M A + bias + relu ----------------
__global__ __launch_bounds__(256) void w3_otrans(const float* __restrict__ bias) {
    const int stb = blockIdx.x;    // 0..340
    const int ocg = blockIdx.y;    // 0..15
    const int t = threadIdx.x;
    const int stl = t & 63;
    const int ocl = t >> 6;
    const int st0 = stb * 64;
    const int st  = st0 + stl;

    int W, lsw, stoff, pixoff;
    if (st0 < 16384)       { W = 256; lsw = 7; stoff = 0;     pixoff = 0; }
    else if (st0 < 20480)  { W = 128; lsw = 6; stoff = 16384; pixoff = 65536; }
    else if (st0 < 21504)  { W = 64;  lsw = 5; stoff = 20480; pixoff = 81920; }
    else if (st0 < 21760)  { W = 32;  lsw = 4; stoff = 21504; pixoff = 86016; }
    else                   { W = 16;  lsw = 3; stoff = 21760; pixoff = 87040; }
    int SW = W >> 1;

    int sidx = st - stoff;
    int sy = sidx >> lsw;
    int sx = sidx & (SW - 1);

#pragma unroll
    for (int o4 = 0; o4 < 4; o4++) {
        int oc = ocg * 16 + ocl * 4 + o4;
        const float* Mp = g_M + (size_t)oc * STTOT + st;
        float Mv[16];
#pragma unroll
        for (int kk = 0; kk < 16; kk++)
            Mv[kk] = Mp[(size_t)kk * 256 * STTOT];

        float e0[4], e1[4];
#pragma unroll
        for (int c = 0; c < 4; c++) {
            e0[c] = Mv[c] + Mv[4 + c] + Mv[8 + c];
            e1[c] = Mv[4 + c] - Mv[8 + c] - Mv[12 + c];
        }
        float o00 = e0[0] + e0[1] + e0[2];
        float o01 = e0[1] - e0[2] - e0[3];
        float o10 = e1[0] + e1[1] + e1[2];
        float o11 = e1[1] - e1[2] - e1[3];

        float bv = bias[oc];
        float* hp = g_h + (size_t)oc * HTOT + pixoff;
        float2 r0, r1;
        r0.x = fmaxf(o00 + bv, 0.f);
        r0.y = fmaxf(o01 + bv, 0.f);
        r1.x = fmaxf(o10 + bv, 0.f);
        r1.y = fmaxf(o11 + bv, 0.f);
        *(float2*)&hp[(2 * sy) * W + 2 * sx]     = r0;
        *(float2*)&hp[(2 * sy + 1) * W + 2 * sx] = r1;
    }
}

// ---------------- heads: 1x1 convs + softmax + decode + min-size ----------------
__global__ __launch_bounds__(128) void heads_decode(
    const float* __restrict__ lw, const float* __restrict__ lb,
    const float* __restrict__ sw, const float* __restrict__ sb)
{
    __shared__ float WL[12][256];
    __shared__ float WS[6][256];
    __shared__ float BL[12], BS[6];
    const int t = threadIdx.x;
    for (int i = t; i < 12 * 256; i += 128) WL[i >> 8][i & 255] = lw[i];
    for (int i = t; i < 6 * 256; i += 128)  WS[i >> 8][i & 255] = sw[i];
    if (t < 12) BL[t] = lb[t];
    if (t < 6)  BS[t] = sb[t];
    __syncthreads();

    const int pix = blockIdx.x * 128 + t;
    int lvl;
    if (pix < 65536) lvl = 0;
    else if (pix < 81920) lvl = 1;
    else if (pix < 86016) lvl = 2;
    else if (pix < 87040) lvl = 3;
    else lvl = 4;
    const int offs[5] = {0, 65536, 81920, 86016, 87040};
    const int lp   = pix - offs[lvl];
    const int lw2  = 8 - lvl;
    const int row  = lp >> lw2;
    const int col  = lp & ((1 << lw2) - 1);
    const int strd = 4 << lvl;

    float acc[18];
#pragma unroll
    for (int j = 0; j < 12; j++) acc[j] = BL[j];
#pragma unroll
    for (int j = 0; j < 6; j++)  acc[12 + j] = BS[j];

    const float* hp = g_h + pix;
#pragma unroll 4
    for (int ic = 0; ic < 256; ic++) {
        float v = hp[(size_t)ic * HTOT];
#pragma unroll
        for (int j = 0; j < 12; j++) acc[j] = fmaf(WL[j][ic], v, acc[j]);
#pragma unroll
        for (int j = 0; j < 6; j++)  acc[12 + j] = fmaf(WS[j][ic], v, acc[12 + j]);
    }

    const float y  = (float)(row * strd);
    const float xx = (float)(col * strd);
    const float sr[3] = {0.70710678118654752f, 1.0f, 1.41421356237309505f};
#pragma unroll
    for (int a = 0; a < 3; a++) {
        float hs = (float)(strd * 8) * sr[a];
        float ws = (float)(strd * 8) * sr[2 - a];
        float a0 = __fadd_rn(y,  -0.5f * hs);
        float a1 = __fadd_rn(xx, -0.5f * ws);
        float a2 = __fadd_rn(y,   0.5f * hs);
        float a3 = __fadd_rn(xx,  0.5f * ws);
        float ah = __fadd_rn(a2, -a0);
        float aw = __fadd_rn(a3, -a1);
        float acy = __fadd_rn(a0, __fmul_rn(0.5f, ah));
        float acx = __fadd_rn(a1, __fmul_rn(0.5f, aw));
        float dy = acc[a * 4 + 0], dx = acc[a * 4 + 1];
        float dh = acc[a * 4 + 2], dw = acc[a * 4 + 3];
        float cy = __fadd_rn(__fmul_rn(dy, ah), acy);
        float cx = __fadd_rn(__fmul_rn(dx, aw), acx);
        float bh = __fmul_rn(expf(dh), ah);
        float bw = __fmul_rn(expf(dw), aw);
        float b0 = fminf(fmaxf(__fadd_rn(cy, -__fmul_rn(0.5f, bh)), 0.f), 1024.f);
        float b1 = fminf(fmaxf(__fadd_rn(cx, -__fmul_rn(0.5f, bw)), 0.f), 1024.f);
        float b2 = fminf(fmaxf(__fadd_rn(cy,  __fmul_rn(0.5f, bh)), 0.f), 1024.f);
        float b3 = fminf(fmaxf(__fadd_rn(cx,  __fmul_rn(0.5f, bw)), 0.f), 1024.f);

        float s0 = acc[12 + a * 2], s1 = acc[12 + a * 2 + 1];
        float m  = fmaxf(s0, s1);
        float e0 = expf(__fadd_rn(s0, -m));
        float e1 = expf(__fadd_rn(s1, -m));
        float fg = __fdiv_rn(e1, __fadd_rn(e0, e1));

        float hh  = __fadd_rn(b2, -b0);
        float ww2 = __fadd_rn(b3, -b1);
        float scv = (hh >= 16.f && ww2 >= 16.f) ? fg : NEGV;

        int aid = pix * 3 + a;
        g_boxes[aid]  = make_float4(b0, b1, b2, b3);
        g_scores[aid] = scv;
    }
}

// ---------------- exact top-6000 via 4-pass radix select ----------------
__device__ __forceinline__ unsigned int fkey(float f) {
    unsigned int u = __float_as_uint(f);
    return u ^ ((u & 0x80000000u) ? 0xFFFFFFFFu : 0x80000000u);
}

__global__ void topk_init() {
    int t = threadIdx.x;
    if (t < 256) g_hist[t] = 0;
    if (t == 0) { g_prefix = 0; g_above = 0; g_remain = PRE_NMS_N; g_ctr = 0; g_tiectr = 0; }
}

__global__ void topk_hist(int shift, unsigned int mask) {
    __shared__ unsigned int sh[256];
    if (threadIdx.x < 256) sh[threadIdx.x] = 0;
    __syncthreads();
    unsigned int pref = g_prefix;
    for (int i = blockIdx.x * blockDim.x + threadIdx.x; i < NANCH; i += gridDim.x * blockDim.x) {
        unsigned int k = fkey(g_scores[i]);
        if ((k & mask) == (pref & mask)) atomicAdd(&sh[(k >> shift) & 255u], 1u);
    }
    __syncthreads();
    if (threadIdx.x < 256 && sh[threadIdx.x]) atomicAdd(&g_hist[threadIdx.x], sh[threadIdx.x]);
}

__global__ void topk_select(int shift) {
    __shared__ unsigned int h[256];
    int t = threadIdx.x;
    h[t] = g_hist[t];
    __syncthreads();
    if (t == 0) {
        unsigned int remain = g_remain;
        unsigned int cum = 0;
        int b = 255;
        for (; b > 0; b--) {
            if (cum + h[b] >= remain) break;
            cum += h[b];
        }
        g_above  = g_above + cum;
        g_remain = remain - cum;
        g_prefix = g_prefix | ((unsigned int)b << shift);
    }
    __syncthreads();
    g_hist[t] = 0;
}

__global__ void topk_compact() {
    unsigned int kt = g_prefix;
    for (int i = blockIdx.x * blockDim.x + threadIdx.x; i < NANCH; i += gridDim.x * blockDim.x) {
        float s = g_scores[i];
        unsigned int k = fkey(s);
        if (k > kt) {
            int p = atomicAdd(&g_ctr, 1);
            g_tb[p] = g_boxes[i];
            g_ts[p] = s;
            g_ti[p] = i;
        } else if (k == kt) {
            int p = atomicAdd(&g_tiectr, 1);
            if (p < TIE_CAP) g_ties[p] = i;
        }
    }
}

__global__ void topk_ties() {
    int need = (int)g_remain;
    int base = (int)g_above;
    int M = g_tiectr;
    if (M > TIE_CAP) M = TIE_CAP;
    for (int i = threadIdx.x; i < M; i += blockDim.x) {
        int idx = g_ties[i];
        int rank = 0;
        for (int j = 0; j < M; j++) rank += (g_ties[j] < idx) ? 1 : 0;
        if (rank < need) {
            int p = base + rank;
            g_tb[p] = g_boxes[idx];
            g_ts[p] = g_scores[idx];
            g_ti[p] = idx;
        }
    }
}

// ---------------- sequential NMS: register-resident, packed u64 keys ----------
__global__ __launch_bounds__(1024) void nms_kernel(float* __restrict__ out) {
    __shared__ u64 rk[32];
    __shared__ int rp[32];
    __shared__ float4 curbox;
    __shared__ float cura;
    __shared__ int curpos, curvalid;

    const int t = threadIdx.x;
    float4 bx[6];
    float  ar[6];
    u64    key[6];

#pragma unroll
    for (int k = 0; k < 6; k++) {
        int i = k * 1024 + t;
        if (i < PRE_NMS_N) {
            float4 b = g_tb[i];
            bx[k] = b;
            ar[k] = __fmul_rn(__fadd_rn(b.z, -b.x), __fadd_rn(b.w, -b.y));
            key[k] = ((u64)fkey(g_ts[i]) << 32) | (u64)(unsigned)(~(unsigned)g_ti[i]);
        } else {
            bx[k] = make_float4(0.f, 0.f, 0.f, 0.f);
            ar[k] = 0.f;
            key[k] = 0ull;
        }
    }
    const unsigned vthr = fkey(NEGV * 0.5f);
    const u64 deadhi = ((u64)fkey(NEGV)) << 32;
    __syncthreads();

    for (int it = 0; it < POST_NMS_N; it++) {
        u64 bk = key[0];
        int bp = t;
#pragma unroll
        for (int k = 1; k < 6; k++) {
            if (key[k] > bk) { bk = key[k]; bp = k * 1024 + t; }
        }
#pragma unroll
        for (int d = 16; d > 0; d >>= 1) {
            u64 ok = __shfl_down_sync(0xffffffffu, bk, d);
            int op = __shfl_down_sync(0xffffffffu, bp, d);
            if (ok > bk) { bk = ok; bp = op; }
        }
        if ((t & 31) == 0) { rk[t >> 5] = bk; rp[t >> 5] = bp; }
        __syncthreads();
        if (t < 32) {
            bk = rk[t]; bp = rp[t];
#pragma unroll
            for (int d = 16; d > 0; d >>= 1) {
                u64 ok = __shfl_down_sync(0xffffffffu, bk, d);
                int op = __shfl_down_sync(0xffffffffu, bp, d);
                if (ok > bk) { bk = ok; bp = op; }
            }
            if (t == 0) {
                curpos = bp;
                int valid = ((unsigned)(bk >> 32) > vthr) ? 1 : 0;
                curvalid = valid;
                if (!valid) {
                    out[it * 4 + 0] = 0.f;
                    out[it * 4 + 1] = 0.f;
                    out[it * 4 + 2] = 0.f;
                    out[it * 4 + 3] = 0.f;
                }
            }
        }
        __syncthreads();
        if (curvalid && t == (curpos & 1023)) {
            int k = curpos >> 10;
            float4 b = bx[k];
            curbox = b;
            cura = ar[k];
            out[it * 4 + 0] = b.x;
            out[it * 4 + 1] = b.y;
            out[it * 4 + 2] = b.z;
            out[it * 4 + 3] = b.w;
            key[k] = deadhi | (key[k] & 0xFFFFFFFFull);
        }
        __syncthreads();
        if (curvalid) {
            float4 bb = curbox;
            float a1 = cura;
#pragma unroll
            for (int k = 0; k < 6; k++) {
                float4 c = bx[k];
                float ty = fmaxf(bb.x, c.x);
                float tx = fmaxf(bb.y, c.y);
                float by = fminf(bb.z, c.z);
                float bxx = fminf(bb.w, c.w);
                float inter = __fmul_rn(fmaxf(__fadd_rn(by, -ty), 0.f),
                                        fmaxf(__fadd_rn(bxx, -tx), 0.f));
                if (inter > 0.f) {
                    float iou = __fdiv_rn(inter,
                        fmaxf(__fadd_rn(__fadd_rn(a1, ar[k]), -inter), 1e-9f));
                    if (iou > 0.7f) key[k] = deadhi | (key[k] & 0xFFFFFFFFull);
                }
            }
        }
    }
}

// ---------------- host launcher ----------------
extern "C" void kernel_launch(void* const* d_in, const int* in_sizes, int n_in,
                              void* d_out, int out_size)
{
    (void)in_sizes; (void)n_in; (void)out_size;
    const float* p2 = (const float*)d_in[0];
    const float* p3 = (const float*)d_in[1];
    const float* p4 = (const float*)d_in[2];
    const float* p5 = (const float*)d_in[3];
    const float* p6 = (const float*)d_in[4];
    const float* conv_w  = (const float*)d_in[5];
    const float* conv_b  = (const float*)d_in[6];
    const float* loc_w   = (const float*)d_in[7];
    const float* loc_b   = (const float*)d_in[8];
    const float* score_w = (const float*)d_in[9];
    const float* score_b = (const float*)d_in[10];
    float* out = (float*)d_out;

    cudaFuncSetAttribute(w2_gemm_k, cudaFuncAttributeMaxDynamicSharedMemorySize, W2_SMEM);

    w0_wtrans<<<256, 256>>>(conv_w);                         // launch 0
    w1_xtrans<<<dim3(341, 64), 256>>>(p2, p3, p4, p5, p6);   // launch 1
    dummy_k<<<1, 32>>>();                                    // launch 2
    w2_gemm_k<<<dim3(341, 16), 256, W2_SMEM>>>();            // launch 3 <- ncu capture slot
    w3_otrans<<<dim3(341, 16), 256>>>(conv_b);

    heads_decode<<<682, 128>>>(loc_w, loc_b, score_w, score_b);

    topk_init<<<1, 256>>>();
    const int shifts[4] = {24, 16, 8, 0};
    const unsigned int masks[4] = {0x00000000u, 0xFF000000u, 0xFFFF0000u, 0xFFFFFF00u};
    for (int p = 0; p < 4; p++) {
        topk_hist<<<512, 256>>>(shifts[p], masks[p]);
        topk_select<<<1, 256>>>(shifts[p]);
    }
    topk_compact<<<512, 256>>>();
    topk_ties<<<1, 1024>>>();

    nms_kernel<<<1, 1024>>>(out);
}